// round 2
// baseline (speedup 1.0000x reference)
#include <cuda_runtime.h>

// ---------------- problem dimensions (fixed by the dataset) ----------------
#define BB   2
#define NV   12000
#define NP   32
#define CINF 5
#define C1   64        // vfe1 out
#define C2   128       // vfe2 out  (= conv1 in channels)
#define D0 20
#define H0 128
#define W0 128
#define S0 (D0*H0*W0)
#define D1 10
#define H1 64
#define W1 64
#define S1 (D1*H1*W1)
#define D2 5
#define H2 32
#define W2 32
#define S2 (D2*H2*W2)
#define D3 3
#define H3 16
#define W3 16
#define S3 (D3*H3*W3)
#define CO1 128
#define CO2 256
#define CO3 256

// ---------------- static scratch (allocation-free rule) ----------------
__device__ float g_f1[BB*NV*C1];
__device__ float g_f2[BB*NV*C2];
__device__ int   g_win[BB*S0];
__device__ float g_y1[BB*CO1*S1];           // conv1 pre-BN, then x2 in-place
__device__ float g_y2[BB*CO2*S2];           // conv2 pre-BN, then x3 in-place
__device__ unsigned char g_act1[BB*S1];
__device__ unsigned char g_act2[BB*S2];
__device__ float g_wT1[27*C2*CO1];
__device__ float g_wT2[27*CO1*CO2];
__device__ float g_wT3[27*CO2*CO3];
__device__ float g_w2T[C1*C2];
__device__ float g_t2[27*CO2];
__device__ float g_t3[27*CO3];
__device__ float g_bg1[CO1];
__device__ float g_bg2[CO2];
__device__ float g_stats[2048];             // packed per-layer sum / sumsq
__device__ float g_a[5*256];                // folded BN scale per stage
__device__ float g_c[5*256];                // folded BN shift per stage

// stats offsets: stage0 vfe1 @0 (C=64), stage1 vfe2 @128 (C=128),
// stage2 conv1 @384 (128), stage3 conv2 @640 (256), stage4 conv3 @1152 (256)

// ---------------- init ----------------
__global__ void k_init() {
    int i = blockIdx.x * blockDim.x + threadIdx.x;
    if (i < 2048) g_stats[i] = 0.f;
    for (int j = i; j < BB*S0; j += gridDim.x * blockDim.x) g_win[j] = -1;
}

// last-write-wins scatter winner (max voxel index per cell)
__global__ void k_winner(const int* __restrict__ vc) {
    int i = blockIdx.x * blockDim.x + threadIdx.x;
    if (i >= BB*NV) return;
    int b = i / NV, v = i % NV;
    int c0 = vc[i*3], c1 = vc[i*3+1], c2 = vc[i*3+2];
    if (c0 < 0 || c0 >= D0 || c1 < 0 || c1 >= H0 || c2 < 0 || c2 >= W0) return;
    atomicMax(&g_win[b*S0 + (c0*H0 + c1)*W0 + c2], v);
}

// ---------------- VFE1 ----------------
// each block: 512 points staged via shared, 64 threads = 64 out channels
__global__ void k_vfe1_stats(const float* __restrict__ x,
                             const float* __restrict__ w1,
                             const float* __restrict__ b1) {
    __shared__ float sx[512*CINF];
    int co = threadIdx.x;  // 64
    int p0 = blockIdx.x * 512;
    for (int i = co; i < 512*CINF; i += 64) sx[i] = x[p0*CINF + i];
    __syncthreads();
    float w0 = w1[co*5], wa = w1[co*5+1], wb = w1[co*5+2], wc = w1[co*5+3], wd = w1[co*5+4];
    float bbv = b1[co];
    float s = 0.f, q = 0.f;
    for (int p = 0; p < 512; p++) {
        const float* xp = &sx[p*5];
        float y = bbv;
        y = fmaf(w0, xp[0], y);
        y = fmaf(wa, xp[1], y);
        y = fmaf(wb, xp[2], y);
        y = fmaf(wc, xp[3], y);
        y = fmaf(wd, xp[4], y);
        s += y; q += y*y;
    }
    atomicAdd(&g_stats[co], s);
    atomicAdd(&g_stats[64+co], q);
}

__global__ void k_bnparam(int off, int C, float invN,
                          const float* __restrict__ g,
                          const float* __restrict__ be, int stage) {
    int c = threadIdx.x;
    if (c >= C) return;
    float mu  = g_stats[off+c] * invN;
    float var = g_stats[off+C+c] * invN - mu*mu;
    float a   = g[c] * rsqrtf(var + 1e-5f);
    g_a[stage*256+c] = a;
    g_c[stage*256+c] = be[c] - mu*a;
}

__global__ void k_vfe1_fwd(const float* __restrict__ x,
                           const float* __restrict__ w1,
                           const float* __restrict__ b1) {
    __shared__ float sx[NP*CINF];
    int bv = blockIdx.x, co = threadIdx.x;  // 64 threads
    for (int i = co; i < NP*CINF; i += 64) sx[i] = x[bv*NP*CINF + i];
    __syncthreads();
    float w0 = w1[co*5], wa = w1[co*5+1], wb = w1[co*5+2], wc = w1[co*5+3], wd = w1[co*5+4];
    float bbv = b1[co];
    float a = g_a[co], c = g_c[co];
    float m = -1e30f;
#pragma unroll
    for (int p = 0; p < NP; p++) {
        const float* xp = &sx[p*5];
        float y = bbv;
        y = fmaf(w0, xp[0], y); y = fmaf(wa, xp[1], y); y = fmaf(wb, xp[2], y);
        y = fmaf(wc, xp[3], y); y = fmaf(wd, xp[4], y);
        m = fmaxf(m, fmaf(y, a, c));
    }
    g_f1[bv*C1 + co] = fmaxf(m, 0.f);
}

// ---------------- VFE2 ----------------
__global__ void k_w2T(const float* __restrict__ w2) {
    int i = blockIdx.x * blockDim.x + threadIdx.x;
    if (i >= C1*C2) return;
    int co = i / C1, k = i % C1;
    g_w2T[k*C2 + co] = w2[co*C1 + k];
}

__global__ void k_vfe2_pre(const float* __restrict__ b2) {
    __shared__ float sf[C1];
    int co = threadIdx.x;  // 128
    float s = 0.f, q = 0.f;
    float bbv = b2[co];
    int r0 = blockIdx.x * 32;
    for (int r = 0; r < 32; r++) {
        int row = r0 + r;
        __syncthreads();
        if (co < C1) sf[co] = g_f1[row*C1 + co];
        __syncthreads();
        float y = bbv;
#pragma unroll 16
        for (int k = 0; k < C1; k++) y = fmaf(sf[k], __ldg(&g_w2T[k*C2 + co]), y);
        g_f2[row*C2 + co] = y;
        s += y; q += y*y;
    }
    atomicAdd(&g_stats[128+co], s);
    atomicAdd(&g_stats[128+C2+co], q);
}

// generic elementwise y = relu(y*a + c); channel = (i/inner)%C
__global__ void k_bnrelu(float* __restrict__ y, int n, int C, int inner, int stage) {
    int i = blockIdx.x * blockDim.x + threadIdx.x;
    if (i >= n) return;
    int c = (i / inner) % C;
    y[i] = fmaxf(fmaf(y[i], g_a[stage*256+c], g_c[stage*256+c]), 0.f);
}

// ---------------- weight transposes: (CO,CI,27) -> (27,CI,CO) ----------------
__global__ void k_wtrans(const float* __restrict__ w, float* __restrict__ wT, int CO, int CI_) {
    int i = blockIdx.x * blockDim.x + threadIdx.x;
    int n = CO * CI_ * 27;
    if (i >= n) return;
    int co = i / (CI_*27);
    int rem = i % (CI_*27);
    int ci = rem / 27, t = rem % 27;
    wT[(t*CI_ + ci)*CO + co] = w[i];
}

// ---------------- conv1: sparse gather over voxel winner map ----------------
__global__ void k_conv1(const float* __restrict__ cb1) {
    __shared__ int svox[27];
    __shared__ float sf[C2];
    __shared__ int sany;
    int pos = blockIdx.x;                 // [0, BB*S1)
    int b = pos / S1, s = pos % S1;
    int od = s / (H1*W1), oh = (s / W1) % H1, ow = s % W1;
    int co = threadIdx.x;                 // 128
    if (co == 0) sany = 0;
    __syncthreads();
    if (co < 27) {
        int kd = co/9, kh = (co/3)%3, kw = co%3;
        int id = 2*od - 1 + kd, ih = 2*oh - 1 + kh, iw = 2*ow - 1 + kw;
        int v = -1;
        if (id >= 0 && id < D0 && ih >= 0 && ih < H0 && iw >= 0 && iw < W0)
            v = g_win[b*S0 + (id*H0 + ih)*W0 + iw];
        svox[co] = v;
        if (v >= 0) atomicOr(&sany, 1);
    }
    __syncthreads();
    float acc = 0.f;
    for (int t = 0; t < 27; t++) {
        int v = svox[t];
        if (v < 0) continue;
        __syncthreads();
        sf[co] = g_f2[(b*NV + v)*C2 + co];
        __syncthreads();
        const float* wp = &g_wT1[t*C2*CO1 + co];
#pragma unroll 16
        for (int ci = 0; ci < C2; ci++) acc = fmaf(sf[ci], __ldg(wp + ci*CO1), acc);
    }
    g_y1[(b*CO1 + co)*S1 + s] = cb1[co] + acc;
    if (co == 0) g_act1[pos] = (unsigned char)(sany ? 1 : 0);
}

// ---------------- per-channel sum/sumsq reduction ----------------
__global__ void k_reduce(const float* __restrict__ y, int C, int Sp, int total, int off) {
    __shared__ float ss[256], sq[256];
    int c = blockIdx.x;
    int tid = threadIdx.x;
    float s = 0.f, q = 0.f;
    int stride = gridDim.y * 256;
    for (int i = blockIdx.y*256 + tid; i < total; i += stride) {
        int b = i / Sp, sp = i % Sp;
        float v = y[(b*C + c)*Sp + sp];
        s += v; q += v*v;
    }
    ss[tid] = s; sq[tid] = q;
    __syncthreads();
    for (int o = 128; o > 0; o >>= 1) {
        if (tid < o) { ss[tid] += ss[tid+o]; sq[tid] += sq[tid+o]; }
        __syncthreads();
    }
    if (tid == 0) {
        atomicAdd(&g_stats[off + c], ss[0]);
        atomicAdd(&g_stats[off + C + c], sq[0]);
    }
}

// ---------------- background values ----------------
__global__ void k_bg1(const float* __restrict__ cb1) {
    int c = threadIdx.x;  // 128
    g_bg1[c] = fmaxf(fmaf(cb1[c], g_a[2*256+c], g_c[2*256+c]), 0.f);
}
__global__ void k_bg2(const float* __restrict__ cb2) {
    int c = threadIdx.x;  // 256
    float u = cb2[c];
#pragma unroll
    for (int t = 0; t < 27; t++) u += g_t2[t*CO2 + c];
    g_bg2[c] = fmaxf(fmaf(u, g_a[3*256+c], g_c[3*256+c]), 0.f);
}

// per-tap constant contribution: t[t][co] = sum_ci bg[ci]*w[co][ci][t]
__global__ void k_tmat(const float* __restrict__ wT, const float* __restrict__ bg,
                       float* __restrict__ tout, int CI_, int CO) {
    int i = blockIdx.x * blockDim.x + threadIdx.x;
    if (i >= 27*CO) return;
    int t = i / CO, co = i % CO;
    float s = 0.f;
    for (int ci = 0; ci < CI_; ci++) s = fmaf(__ldg(&bg[ci]), wT[(t*CI_ + ci)*CO + co], s);
    tout[i] = s;
}

// ---------------- constant-background conv (conv2, conv3) ----------------
template<int CI_, int CO, int Din, int Hin, int Win, int Dout, int Hout, int Wout>
__global__ void k_conv(const float* __restrict__ xin, const unsigned char* __restrict__ actin,
                       const float* __restrict__ tC, const float* __restrict__ bias,
                       const float* __restrict__ wT, const float* __restrict__ bg,
                       float* __restrict__ yout, unsigned char* actout) {
    __shared__ float sdx[CI_];
    __shared__ int stap[27];
    __shared__ int sflags;
    constexpr int Sin = Din*Hin*Win;
    constexpr int Sout = Dout*Hout*Wout;
    int pos = blockIdx.x;                 // [0, BB*Sout)
    int b = pos / Sout, s = pos % Sout;
    int od = s / (Hout*Wout), oh = (s / Wout) % Hout, ow = s % Wout;
    int co = threadIdx.x;                 // CO threads
    if (co == 0) sflags = 0;
    __syncthreads();
    if (co < 27) {
        int kd = co/9, kh = (co/3)%3, kw = co%3;
        int id = 2*od - 1 + kd, ih = 2*oh - 1 + kh, iw = 2*ow - 1 + kw;
        int r;
        if (id < 0 || id >= Din || ih < 0 || ih >= Hin || iw < 0 || iw >= Win) {
            r = -2; atomicOr(&sflags, 2);                 // padded tap (border)
        } else {
            int cell = (id*Hin + ih)*Win + iw;
            if (actin[b*Sin + cell]) { r = cell; atomicOr(&sflags, 1); }
            else r = -1;                                   // background tap
        }
        stap[co] = r;
    }
    __syncthreads();
    float acc = bias[co];
#pragma unroll
    for (int t = 0; t < 27; t++)
        if (stap[t] != -2) acc += __ldg(&tC[t*CO + co]);   // constant part (valid taps)
    for (int t = 0; t < 27; t++) {
        int cell = stap[t];
        if (cell < 0) continue;                            // uniform branch
        __syncthreads();
        for (int i = co; i < CI_; i += CO)
            sdx[i] = xin[(b*CI_ + i)*Sin + cell] - bg[i];  // delta vs background
        __syncthreads();
        const float* wp = &wT[t*CI_*CO + co];
#pragma unroll 16
        for (int ci = 0; ci < CI_; ci++) acc = fmaf(sdx[ci], __ldg(wp + ci*CO), acc);
    }
    yout[(b*CO + co)*Sout + s] = acc;
    if (actout && co == 0) actout[pos] = (unsigned char)(sflags != 0);
}

// ---------------- launch ----------------
extern "C" void kernel_launch(void* const* d_in, const int* in_sizes, int n_in,
                              void* d_out, int out_size) {
    // input layout: 0 voxel_features, 1 voxel_coords, [2,3,4 = D,H,W scalars if present]
    int base = (n_in >= 25) ? 5 : 2;
    const float* vf  = (const float*)d_in[0];
    const int*   vc  = (const int*)d_in[1];
    const float* w1  = (const float*)d_in[base+0];
    const float* b1  = (const float*)d_in[base+1];
    const float* g1  = (const float*)d_in[base+2];
    const float* be1 = (const float*)d_in[base+3];
    const float* w2  = (const float*)d_in[base+4];
    const float* b2  = (const float*)d_in[base+5];
    const float* g2  = (const float*)d_in[base+6];
    const float* be2 = (const float*)d_in[base+7];
    const float* cw1 = (const float*)d_in[base+8];
    const float* cb1 = (const float*)d_in[base+9];
    const float* cg1 = (const float*)d_in[base+10];
    const float* cbe1= (const float*)d_in[base+11];
    const float* cw2 = (const float*)d_in[base+12];
    const float* cb2 = (const float*)d_in[base+13];
    const float* cg2 = (const float*)d_in[base+14];
    const float* cbe2= (const float*)d_in[base+15];
    const float* cw3 = (const float*)d_in[base+16];
    const float* cb3 = (const float*)d_in[base+17];
    const float* cg3 = (const float*)d_in[base+18];
    const float* cbe3= (const float*)d_in[base+19];
    float* out = (float*)d_out;

    // device symbol addresses (no allocation; lookup only)
    float *p_f2, *p_y1, *p_y2, *p_wT1, *p_wT2, *p_wT3, *p_t2, *p_t3, *p_bg1, *p_bg2;
    unsigned char *p_act1, *p_act2;
    cudaGetSymbolAddress((void**)&p_f2,  g_f2);
    cudaGetSymbolAddress((void**)&p_y1,  g_y1);
    cudaGetSymbolAddress((void**)&p_y2,  g_y2);
    cudaGetSymbolAddress((void**)&p_wT1, g_wT1);
    cudaGetSymbolAddress((void**)&p_wT2, g_wT2);
    cudaGetSymbolAddress((void**)&p_wT3, g_wT3);
    cudaGetSymbolAddress((void**)&p_t2,  g_t2);
    cudaGetSymbolAddress((void**)&p_t3,  g_t3);
    cudaGetSymbolAddress((void**)&p_bg1, g_bg1);
    cudaGetSymbolAddress((void**)&p_bg2, g_bg2);
    cudaGetSymbolAddress((void**)&p_act1, g_act1);
    cudaGetSymbolAddress((void**)&p_act2, g_act2);

    k_init<<<2560, 256>>>();
    k_winner<<<(BB*NV + 255)/256, 256>>>(vc);

    // VFE1
    k_vfe1_stats<<<1500, 64>>>(vf, w1, b1);
    k_bnparam<<<1, 64>>>(0, 64, 1.f/768000.f, g1, be1, 0);
    k_vfe1_fwd<<<BB*NV, 64>>>(vf, w1, b1);

    // VFE2
    k_w2T<<<(C1*C2 + 255)/256, 256>>>(w2);
    k_vfe2_pre<<<750, 128>>>(b2);
    k_bnparam<<<1, 128>>>(128, 128, 1.f/24000.f, g2, be2, 1);
    k_bnrelu<<<(BB*NV*C2 + 255)/256, 256>>>(p_f2, BB*NV*C2, 128, 1, 1);

    // weight transposes
    k_wtrans<<<(CO1*C2*27 + 255)/256, 256>>>(cw1, p_wT1, CO1, C2);
    k_wtrans<<<(CO2*CO1*27 + 255)/256, 256>>>(cw2, p_wT2, CO2, CO1);
    k_wtrans<<<(CO3*CO2*27 + 255)/256, 256>>>(cw3, p_wT3, CO3, CO2);

    // conv1 (sparse gather) + BN
    k_conv1<<<BB*S1, 128>>>(cb1);
    {
        dim3 grd(128, 8);
        k_reduce<<<grd, 256>>>(p_y1, 128, S1, BB*S1, 384);
    }
    k_bnparam<<<1, 128>>>(384, 128, 1.f/(float)(BB*S1), cg1, cbe1, 2);
    k_bg1<<<1, 128>>>(cb1);
    k_bnrelu<<<(BB*CO1*S1 + 255)/256, 256>>>(p_y1, BB*CO1*S1, 128, S1, 2);

    // conv2 (constant background + delta gather) + BN
    k_tmat<<<27, 256>>>(p_wT2, p_bg1, p_t2, CO1, CO2);
    k_conv<CO1, CO2, D1, H1, W1, D2, H2, W2><<<BB*S2, CO2>>>(
        p_y1, p_act1, p_t2, cb2, p_wT2, p_bg1, p_y2, p_act2);
    {
        dim3 grd(256, 2);
        k_reduce<<<grd, 256>>>(p_y2, 256, S2, BB*S2, 640);
    }
    k_bnparam<<<1, 256>>>(640, 256, 1.f/(float)(BB*S2), cg2, cbe2, 3);
    k_bg2<<<1, 256>>>(cb2);
    k_bnrelu<<<(BB*CO2*S2 + 255)/256, 256>>>(p_y2, BB*CO2*S2, 256, S2, 3);

    // conv3 (constant background + delta gather) + BN, writes d_out
    k_tmat<<<27, 256>>>(p_wT3, p_bg2, p_t3, CO2, CO3);
    k_conv<CO2, CO3, D2, H2, W2, D3, H3, W3><<<BB*S3, CO3>>>(
        p_y2, p_act2, p_t3, cb3, p_wT3, p_bg2, out, (unsigned char*)0);
    {
        dim3 grd(256, 1);
        k_reduce<<<grd, 256>>>(out, 256, S3, BB*S3, 1152);
    }
    k_bnparam<<<1, 256>>>(1152, 256, 1.f/(float)(BB*S3), cg3, cbe3, 4);
    k_bnrelu<<<(BB*CO3*S3 + 255)/256, 256>>>(out, BB*CO3*S3, 256, S3, 4);
}

// round 4
// speedup vs baseline: 1.2938x; 1.2938x over previous
#include <cuda_runtime.h>

// ---------------- problem dimensions (fixed by the dataset) ----------------
#define BB   2
#define NV   12000
#define NP   32
#define CINF 5
#define C1   64        // vfe1 out
#define C2   128       // vfe2 out  (= conv1 in channels)
#define D0 20
#define H0 128
#define W0 128
#define S0 (D0*H0*W0)
#define D1 10
#define H1 64
#define W1 64
#define S1 (D1*H1*W1)
#define D2 5
#define H2 32
#define W2 32
#define S2 (D2*H2*W2)
#define D3 3
#define H3 16
#define W3 16
#define S3 (D3*H3*W3)
#define CO1 128
#define CO2 256
#define CO3 256

// stats offsets: vfe1 @0 (64), vfe2 @128 (128), conv1 @384 (128),
// conv2 @640 (256), conv3 @1152 (256)

// ---------------- static scratch (allocation-free rule) ----------------
__device__ float g_f1[BB*NV*C1];
__device__ float g_f2[BB*NV*C2];
__device__ int   g_win[BB*S0];
__device__ int   g_act1[BB*S1];
__device__ int   g_idx1[BB*S1];
__device__ int   g_act2[BB*S2];
__device__ int   g_idx2[BB*S2];
__device__ int   g_list1[BB*S1];
__device__ int   g_list2[BB*S2];
__device__ int   g_cnt[16];                 // [0]=cnt1 [1]=cnt2 [2..9]=cls counts
__device__ float g_ya1[BB*S1*CO1];          // compact active1 rows, channel-last
__device__ float g_ya2[BB*S2*CO2];          // compact active2 rows, channel-last
__device__ float g_wT1[27*C2*CO1];
__device__ float g_wT2[27*CO1*CO2];
__device__ float g_wT3[27*CO2*CO3];
__device__ float g_w2T[C1*C2];
__device__ float g_t2[27*CO2];
__device__ float g_u2[8*CO2];               // per-class conv2 inactive pre-BN const
__device__ float g_x2bg[8*CO2];             // per-class conv2 post-BN background
__device__ float g_t3c[8*27*CO3];           // per-class per-tap conv3 constants
__device__ float g_bg1[CO1];
__device__ float g_stats[2048];
__device__ float g_a[5*256];
__device__ float g_c[5*256];

// ---------------- init ----------------
__global__ void k_init() {
    int tid = blockIdx.x * blockDim.x + threadIdx.x;
    int stride = gridDim.x * blockDim.x;
    for (int j = tid; j < BB*S0; j += stride) g_win[j] = -1;
    for (int j = tid; j < BB*S1; j += stride) { g_act1[j] = 0; g_idx1[j] = -1; }
    for (int j = tid; j < BB*S2; j += stride) { g_act2[j] = 0; g_idx2[j] = -1; }
    if (tid < 2048) g_stats[tid] = 0.f;
    if (tid < 16) g_cnt[tid] = 0;
}

// last-write-wins scatter winner (max voxel index per cell)
__global__ void k_winner(const int* __restrict__ vc) {
    int i = blockIdx.x * blockDim.x + threadIdx.x;
    if (i >= BB*NV) return;
    int b = i / NV, v = i % NV;
    int c0 = vc[i*3], c1 = vc[i*3+1], c2 = vc[i*3+2];
    if (c0 < 0 || c0 >= D0 || c1 < 0 || c1 >= H0 || c2 < 0 || c2 >= W0) return;
    atomicMax(&g_win[b*S0 + (c0*H0 + c1)*W0 + c2], v);
}

// mark conv1 outputs covered by any occupied input cell (input-centric, <=8 each)
__global__ void k_mark1(const int* __restrict__ vc) {
    int i = blockIdx.x * blockDim.x + threadIdx.x;
    if (i >= BB*NV) return;
    int b = i / NV;
    int c0 = vc[i*3], c1 = vc[i*3+1], c2 = vc[i*3+2];
    if (c0 < 0 || c0 >= D0 || c1 < 0 || c1 >= H0 || c2 < 0 || c2 >= W0) return;
    int dlo = c0 >> 1, dhi = min((c0+1) >> 1, D1-1);
    int hlo = c1 >> 1, hhi = min((c1+1) >> 1, H1-1);
    int wlo = c2 >> 1, whi = min((c2+1) >> 1, W1-1);
    for (int d = dlo; d <= dhi; d++)
        for (int h = hlo; h <= hhi; h++)
            for (int w = wlo; w <= whi; w++)
                g_act1[b*S1 + (d*H1 + h)*W1 + w] = 1;
}

// ---------------- VFE1 ----------------
__global__ void k_vfe1_stats(const float* __restrict__ x,
                             const float* __restrict__ w1,
                             const float* __restrict__ b1) {
    __shared__ float sx[512*CINF];
    int co = threadIdx.x;  // 64
    int p0 = blockIdx.x * 512;
    for (int i = co; i < 512*CINF; i += 64) sx[i] = x[p0*CINF + i];
    __syncthreads();
    float w0 = w1[co*5], wa = w1[co*5+1], wb = w1[co*5+2], wc = w1[co*5+3], wd = w1[co*5+4];
    float bbv = b1[co];
    float s = 0.f, q = 0.f;
    for (int p = 0; p < 512; p++) {
        const float* xp = &sx[p*5];
        float y = bbv;
        y = fmaf(w0, xp[0], y); y = fmaf(wa, xp[1], y); y = fmaf(wb, xp[2], y);
        y = fmaf(wc, xp[3], y); y = fmaf(wd, xp[4], y);
        s += y; q += y*y;
    }
    atomicAdd(&g_stats[co], s);
    atomicAdd(&g_stats[64+co], q);
}

__global__ void k_bnparam(int off, int C, float invN,
                          const float* __restrict__ g,
                          const float* __restrict__ be, int stage) {
    int c = threadIdx.x;
    if (c >= C) return;
    float mu  = g_stats[off+c] * invN;
    float var = g_stats[off+C+c] * invN - mu*mu;
    float a   = g[c] * rsqrtf(var + 1e-5f);
    g_a[stage*256+c] = a;
    g_c[stage*256+c] = be[c] - mu*a;
}

__global__ void k_vfe1_fwd(const float* __restrict__ x,
                           const float* __restrict__ w1,
                           const float* __restrict__ b1) {
    __shared__ float sx[NP*CINF];
    int bv = blockIdx.x, co = threadIdx.x;  // 64 threads
    for (int i = co; i < NP*CINF; i += 64) sx[i] = x[bv*NP*CINF + i];
    __syncthreads();
    float w0 = w1[co*5], wa = w1[co*5+1], wb = w1[co*5+2], wc = w1[co*5+3], wd = w1[co*5+4];
    float bbv = b1[co];
    float a = g_a[co], c = g_c[co];
    float m = -1e30f;
#pragma unroll
    for (int p = 0; p < NP; p++) {
        const float* xp = &sx[p*5];
        float y = bbv;
        y = fmaf(w0, xp[0], y); y = fmaf(wa, xp[1], y); y = fmaf(wb, xp[2], y);
        y = fmaf(wc, xp[3], y); y = fmaf(wd, xp[4], y);
        m = fmaxf(m, fmaf(y, a, c));
    }
    g_f1[bv*C1 + co] = fmaxf(m, 0.f);
}

// ---------------- VFE2 ----------------
__global__ void k_w2T(const float* __restrict__ w2) {
    int i = blockIdx.x * blockDim.x + threadIdx.x;
    if (i >= C1*C2) return;
    int k = i / C2, co = i % C2;               // output index, coalesced write
    g_w2T[i] = __ldg(&w2[co*C1 + k]);
}

__global__ void k_vfe2_pre(const float* __restrict__ b2) {
    __shared__ float sf[C1];
    int co = threadIdx.x;  // 128
    float s = 0.f, q = 0.f;
    float bbv = b2[co];
    int r0 = blockIdx.x * 32;
    for (int r = 0; r < 32; r++) {
        int row = r0 + r;
        __syncthreads();
        if (co < C1) sf[co] = g_f1[row*C1 + co];
        __syncthreads();
        float y = bbv;
#pragma unroll 16
        for (int k = 0; k < C1; k++) y = fmaf(sf[k], __ldg(&g_w2T[k*C2 + co]), y);
        g_f2[row*C2 + co] = y;
        s += y; q += y*y;
    }
    atomicAdd(&g_stats[128+co], s);
    atomicAdd(&g_stats[128+C2+co], q);
}

// elementwise y = relu(y*a + c); channel = (i/inner)%C
__global__ void k_bnrelu(float* __restrict__ y, int n, int C, int inner, int stage) {
    int i = blockIdx.x * blockDim.x + threadIdx.x;
    if (i >= n) return;
    int c = (i / inner) % C;
    y[i] = fmaxf(fmaf(y[i], g_a[stage*256+c], g_c[stage*256+c]), 0.f);
}

// bnrelu over compact buffer sized by device counter
__global__ void k_xa(float* __restrict__ y, int C, int stage, int cntIdx) {
    int n = g_cnt[cntIdx] * C;
    int stride = gridDim.x * blockDim.x;
    for (int i = blockIdx.x * blockDim.x + threadIdx.x; i < n; i += stride) {
        int c = i % C;   // C power of 2
        y[i] = fmaxf(fmaf(y[i], g_a[stage*256+c], g_c[stage*256+c]), 0.f);
    }
}

// weight transpose (CO,CI,27) -> (27,CI,CO), coalesced writes
__global__ void k_wtrans(const float* __restrict__ w, float* __restrict__ wT, int CO, int CI_) {
    int i = blockIdx.x * blockDim.x + threadIdx.x;
    int n = 27 * CI_ * CO;
    if (i >= n) return;
    int co = i % CO;
    int rem = i / CO;
    int ci = rem % CI_, t = rem / CI_;
    wT[i] = __ldg(&w[(co*CI_ + ci)*27 + t]);
}

// ---------------- compaction ----------------
__global__ void k_compact1() {
    int j = blockIdx.x * blockDim.x + threadIdx.x;
    if (j >= BB*S1) return;
    if (g_act1[j]) {
        int p = atomicAdd(&g_cnt[0], 1);
        g_list1[p] = j;
        g_idx1[j] = p;
    }
}

__global__ void k_mark2() {
    int cnt = g_cnt[0];
    int stride = gridDim.x * blockDim.x;
    for (int it = blockIdx.x * blockDim.x + threadIdx.x; it < cnt; it += stride) {
        int j = g_list1[it];
        int b = j / S1, s = j % S1;
        int d = s / (H1*W1), h = (s / W1) % H1, w = s % W1;
        int dlo = d >> 1, dhi = min((d+1) >> 1, D2-1);
        int hlo = h >> 1, hhi = min((h+1) >> 1, H2-1);
        int wlo = w >> 1, whi = min((w+1) >> 1, W2-1);
        for (int dd = dlo; dd <= dhi; dd++)
            for (int hh = hlo; hh <= hhi; hh++)
                for (int ww = wlo; ww <= whi; ww++)
                    g_act2[b*S2 + (dd*H2 + hh)*W2 + ww] = 1;
    }
}

__global__ void k_compact2() {
    int j = blockIdx.x * blockDim.x + threadIdx.x;
    if (j >= BB*S2) return;
    if (g_act2[j]) {
        int p = atomicAdd(&g_cnt[1], 1);
        g_list2[p] = j;
        g_idx2[j] = p;
        int s = j % S2;
        int od = s / (H2*W2), oh = (s / W2) % H2, ow = s % W2;
        int cls = (od==0 ? 1 : 0) | (oh==0 ? 2 : 0) | (ow==0 ? 4 : 0);
        atomicAdd(&g_cnt[2+cls], 1);
    }
}

// ---------------- conv1 at active cells only ----------------
__global__ void k_conv1a(const float* __restrict__ cb1) {
    __shared__ float sf[C2];
    __shared__ int svox[27];
    int cnt = g_cnt[0];
    int co = threadIdx.x;  // 128
    for (int it = blockIdx.x; it < cnt; it += gridDim.x) {
        int j = g_list1[it];
        int b = j / S1, s = j % S1;
        int od = s / (H1*W1), oh = (s / W1) % H1, ow = s % W1;
        __syncthreads();
        if (co < 27) {
            int kd = co/9, kh = (co/3)%3, kw = co%3;
            int id = 2*od - 1 + kd, ih = 2*oh - 1 + kh, iw = 2*ow - 1 + kw;
            int v = -1;
            if (id >= 0 && id < D0 && ih >= 0 && ih < H0 && iw >= 0 && iw < W0)
                v = g_win[b*S0 + (id*H0 + ih)*W0 + iw];
            svox[co] = v;
        }
        __syncthreads();
        float acc = cb1[co];
        for (int t = 0; t < 27; t++) {
            int v = svox[t];
            if (v < 0) continue;
            __syncthreads();
            sf[co] = g_f2[(b*NV + v)*C2 + co];
            __syncthreads();
            const float* wp = &g_wT1[t*C2*CO1 + co];
#pragma unroll 16
            for (int ci = 0; ci < C2; ci++) acc = fmaf(sf[ci], __ldg(wp + ci*CO1), acc);
        }
        g_ya1[it*CO1 + co] = acc;   // channel-last, coalesced
    }
}

// reduce compact ya1 (rows x 128)
__global__ void k_reduce_c1() {
    __shared__ float ss[256], sq[256];
    int tid = threadIdx.x;
    int c = tid & 127, half = tid >> 7;
    int cnt = g_cnt[0];
    float s = 0.f, q = 0.f;
    for (int r = blockIdx.x*2 + half; r < cnt; r += gridDim.x*2) {
        float v = g_ya1[r*CO1 + c];
        s += v; q += v*v;
    }
    ss[tid] = s; sq[tid] = q;
    __syncthreads();
    if (tid < 128) {
        s = ss[tid] + ss[tid+128];
        q = sq[tid] + sq[tid+128];
        atomicAdd(&g_stats[384 + tid], s);
        atomicAdd(&g_stats[384 + 128 + tid], q);
    }
}

// stage2 BN finalize (analytic inactive term) + bg1
__global__ void k_bn2fin(const float* __restrict__ cb1,
                         const float* __restrict__ cg1,
                         const float* __restrict__ cbe1) {
    int c = threadIdx.x;  // 128
    float nin = (float)(BB*S1 - g_cnt[0]);
    float bb = cb1[c];
    float sum = g_stats[384+c] + nin*bb;
    float sq  = g_stats[384+128+c] + nin*bb*bb;
    float invN = 1.f / (float)(BB*S1);
    float mu = sum*invN;
    float var = sq*invN - mu*mu;
    float a = cg1[c] * rsqrtf(var + 1e-5f);
    float cc = cbe1[c] - mu*a;
    g_a[2*256+c] = a; g_c[2*256+c] = cc;
    g_bg1[c] = fmaxf(fmaf(bb, a, cc), 0.f);
}

// per-tap constant: t2[t][co] = sum_ci bg1[ci]*w2[t][ci][co]
__global__ void k_tmat2() {
    int t = blockIdx.x, co = threadIdx.x;  // 27 x 256
    float s = 0.f;
    const float* wp = &g_wT2[t*CO1*CO2 + co];
    for (int ci = 0; ci < CO1; ci++) s = fmaf(__ldg(&g_bg1[ci]), __ldg(wp + ci*CO2), s);
    g_t2[t*CO2 + co] = s;
}

// ---------------- conv2 at active cells only ----------------
__global__ void k_conv2a(const float* __restrict__ cb2) {
    __shared__ float sdx[CO1];
    __shared__ int stap[27];
    int cnt = g_cnt[1];
    int co = threadIdx.x;  // 256
    for (int it = blockIdx.x; it < cnt; it += gridDim.x) {
        int j = g_list2[it];
        int b = j / S2, s = j % S2;
        int od = s / (H2*W2), oh = (s / W2) % H2, ow = s % W2;
        __syncthreads();
        if (co < 27) {
            int kd = co/9, kh = (co/3)%3, kw = co%3;
            int id = 2*od - 1 + kd, ih = 2*oh - 1 + kh, iw = 2*ow - 1 + kw;
            int r = -2;
            if (id >= 0 && id < D1 && ih >= 0 && ih < H1 && iw >= 0 && iw < W1)
                r = g_idx1[b*S1 + (id*H1 + ih)*W1 + iw];
            stap[co] = r;
        }
        __syncthreads();
        float acc = cb2[co];
#pragma unroll
        for (int t = 0; t < 27; t++)
            if (stap[t] != -2) acc += __ldg(&g_t2[t*CO2 + co]);
        for (int t = 0; t < 27; t++) {
            int r = stap[t];
            if (r < 0) continue;
            __syncthreads();
            if (co < CO1) sdx[co] = g_ya1[r*CO1 + co] - g_bg1[co];
            __syncthreads();
            const float* wp = &g_wT2[t*CO1*CO2 + co];
#pragma unroll 16
            for (int ci = 0; ci < CO1; ci++) acc = fmaf(sdx[ci], __ldg(wp + ci*CO2), acc);
        }
        g_ya2[it*CO2 + co] = acc;
    }
}

__global__ void k_reduce_c2() {
    int c = threadIdx.x;  // 256
    int cnt = g_cnt[1];
    float s = 0.f, q = 0.f;
    for (int r = blockIdx.x; r < cnt; r += gridDim.x) {
        float v = g_ya2[r*CO2 + c];
        s += v; q += v*v;
    }
    atomicAdd(&g_stats[640 + c], s);
    atomicAdd(&g_stats[640 + 256 + c], q);
}

// per-class conv2 inactive constant
__global__ void k_u2(const float* __restrict__ cb2) {
    int cls = blockIdx.x, c = threadIdx.x;  // 8 x 256
    float u = cb2[c];
#pragma unroll
    for (int t = 0; t < 27; t++) {
        int kd = t/9, kh = (t/3)%3, kw = t%3;
        bool valid = !((cls & 1) && kd == 0) && !((cls & 2) && kh == 0) && !((cls & 4) && kw == 0);
        if (valid) u += __ldg(&g_t2[t*CO2 + c]);
    }
    g_u2[cls*CO2 + c] = u;
}

// stage3 BN finalize (class-analytic inactive) + per-class post-BN backgrounds
__global__ void k_bn3fin(const float* __restrict__ cg2,
                         const float* __restrict__ cbe2) {
    int c = threadIdx.x;  // 256
    float sum = g_stats[640+c], sq = g_stats[640+256+c];
    float uv[8];
#pragma unroll
    for (int cls = 0; cls < 8; cls++) {
        float tot = (float)(BB * ((cls&1)?1:(D2-1)) * ((cls&2)?1:(H2-1)) * ((cls&4)?1:(W2-1)));
        float nin = tot - (float)g_cnt[2+cls];
        float u = g_u2[cls*CO2 + c];
        uv[cls] = u;
        sum += nin*u; sq += nin*u*u;
    }
    float invN = 1.f / (float)(BB*S2);
    float mu = sum*invN;
    float var = sq*invN - mu*mu;
    float a = cg2[c] * rsqrtf(var + 1e-5f);
    float cc = cbe2[c] - mu*a;
    g_a[3*256+c] = a; g_c[3*256+c] = cc;
#pragma unroll
    for (int cls = 0; cls < 8; cls++)
        g_x2bg[cls*CO2 + c] = fmaxf(fmaf(uv[cls], a, cc), 0.f);
}

// per-class per-tap conv3 constants: t3c[cls][t][co] = sum_ci x2bg[cls][ci]*w3[t][ci][co]
__global__ void k_t3c() {
    int cls = blockIdx.x / 27, t = blockIdx.x % 27;  // 216 blocks
    int co = threadIdx.x;  // 256
    float s = 0.f;
    const float* xb = &g_x2bg[cls*CO2];
    const float* wp = &g_wT3[t*CO2*CO3 + co];
    for (int ci = 0; ci < CO2; ci++) s = fmaf(__ldg(&xb[ci]), __ldg(wp + ci*CO3), s);
    g_t3c[(cls*27 + t)*CO3 + co] = s;
}

// ---------------- conv3 dense (output is small) ----------------
__global__ void k_conv3(const float* __restrict__ cb3, float* __restrict__ out) {
    __shared__ float sdx[CO2];
    __shared__ int stap[27], scls[27];
    int pos = blockIdx.x;                 // [0, BB*S3)
    int b = pos / S3, s = pos % S3;
    int od = s / (H3*W3), oh = (s / W3) % H3, ow = s % W3;
    int co = threadIdx.x;  // 256
    if (co < 27) {
        int kd = co/9, kh = (co/3)%3, kw = co%3;
        int id = 2*od - 1 + kd, ih = 2*oh - 1 + kh, iw = 2*ow - 1 + kw;
        int r = -2, cl = 0;
        if (id >= 0 && id < D2 && ih >= 0 && ih < H2 && iw >= 0 && iw < W2) {
            int cell = (id*H2 + ih)*W2 + iw;
            r = g_idx2[b*S2 + cell];
            cl = (id==0 ? 1 : 0) | (ih==0 ? 2 : 0) | (iw==0 ? 4 : 0);
        }
        stap[co] = r; scls[co] = cl;
    }
    __syncthreads();
    float acc = cb3[co];
#pragma unroll
    for (int t = 0; t < 27; t++)
        if (stap[t] != -2) acc += __ldg(&g_t3c[(scls[t]*27 + t)*CO3 + co]);
    for (int t = 0; t < 27; t++) {
        int r = stap[t];
        if (r < 0) continue;
        int cl = scls[t];
        __syncthreads();
        sdx[co] = g_ya2[r*CO2 + co] - g_x2bg[cl*CO2 + co];
        __syncthreads();
        const float* wp = &g_wT3[t*CO2*CO3 + co];
#pragma unroll 16
        for (int ci = 0; ci < CO2; ci++) acc = fmaf(sdx[ci], __ldg(wp + ci*CO3), acc);
    }
    out[(b*CO3 + co)*S3 + s] = acc;
}

// per-channel stats over dense out (one block per channel)
__global__ void k_reduce_out(const float* __restrict__ y) {
    __shared__ float ss[256], sq[256];
    int c = blockIdx.x, tid = threadIdx.x;
    float s = 0.f, q = 0.f;
    for (int i = tid; i < BB*S3; i += 256) {
        int b = i / S3, sp = i % S3;
        float v = y[(b*CO3 + c)*S3 + sp];
        s += v; q += v*v;
    }
    ss[tid] = s; sq[tid] = q;
    __syncthreads();
    for (int o = 128; o > 0; o >>= 1) {
        if (tid < o) { ss[tid] += ss[tid+o]; sq[tid] += sq[tid+o]; }
        __syncthreads();
    }
    if (tid == 0) { g_stats[1152 + c] = ss[0]; g_stats[1152 + 256 + c] = sq[0]; }
}

// ---------------- launch ----------------
extern "C" void kernel_launch(void* const* d_in, const int* in_sizes, int n_in,
                              void* d_out, int out_size) {
    int base = (n_in >= 25) ? 5 : 2;
    const float* vf  = (const float*)d_in[0];
    const int*   vc  = (const int*)d_in[1];
    const float* w1  = (const float*)d_in[base+0];
    const float* b1  = (const float*)d_in[base+1];
    const float* g1  = (const float*)d_in[base+2];
    const float* be1 = (const float*)d_in[base+3];
    const float* w2  = (const float*)d_in[base+4];
    const float* b2  = (const float*)d_in[base+5];
    const float* g2  = (const float*)d_in[base+6];
    const float* be2 = (const float*)d_in[base+7];
    const float* cw1 = (const float*)d_in[base+8];
    const float* cb1 = (const float*)d_in[base+9];
    const float* cg1 = (const float*)d_in[base+10];
    const float* cbe1= (const float*)d_in[base+11];
    const float* cw2 = (const float*)d_in[base+12];
    const float* cb2 = (const float*)d_in[base+13];
    const float* cg2 = (const float*)d_in[base+14];
    const float* cbe2= (const float*)d_in[base+15];
    const float* cw3 = (const float*)d_in[base+16];
    const float* cb3 = (const float*)d_in[base+17];
    const float* cg3 = (const float*)d_in[base+18];
    const float* cbe3= (const float*)d_in[base+19];
    float* out = (float*)d_out;

    float *p_f2, *p_ya1, *p_ya2, *p_wT1, *p_wT2, *p_wT3;
    cudaGetSymbolAddress((void**)&p_f2,  g_f2);
    cudaGetSymbolAddress((void**)&p_ya1, g_ya1);
    cudaGetSymbolAddress((void**)&p_ya2, g_ya2);
    cudaGetSymbolAddress((void**)&p_wT1, g_wT1);
    cudaGetSymbolAddress((void**)&p_wT2, g_wT2);
    cudaGetSymbolAddress((void**)&p_wT3, g_wT3);

    k_init<<<1024, 256>>>();
    k_winner<<<(BB*NV + 255)/256, 256>>>(vc);
    k_mark1<<<(BB*NV + 255)/256, 256>>>(vc);

    // VFE1
    k_vfe1_stats<<<1500, 64>>>(vf, w1, b1);
    k_bnparam<<<1, 64>>>(0, 64, 1.f/768000.f, g1, be1, 0);
    k_vfe1_fwd<<<BB*NV, 64>>>(vf, w1, b1);

    // VFE2
    k_w2T<<<(C1*C2 + 255)/256, 256>>>(w2);
    k_vfe2_pre<<<750, 128>>>(b2);
    k_bnparam<<<1, 128>>>(128, 128, 1.f/24000.f, g2, be2, 1);
    k_bnrelu<<<(BB*NV*C2 + 255)/256, 256>>>(p_f2, BB*NV*C2, 128, 1, 1);

    // weight transposes (coalesced writes)
    k_wtrans<<<(27*C2*CO1 + 255)/256, 256>>>(cw1, p_wT1, CO1, C2);
    k_wtrans<<<(27*CO1*CO2 + 255)/256, 256>>>(cw2, p_wT2, CO2, CO1);
    k_wtrans<<<(27*CO2*CO3 + 255)/256, 256>>>(cw3, p_wT3, CO3, CO2);

    // conv1 sparse
    k_compact1<<<(BB*S1 + 255)/256, 256>>>();
    k_conv1a<<<2048, 128>>>(cb1);
    k_reduce_c1<<<240, 256>>>();
    k_bn2fin<<<1, 128>>>(cb1, cg1, cbe1);
    k_xa<<<1024, 256>>>(p_ya1, CO1, 2, 0);

    // conv2 sparse
    k_tmat2<<<27, 256>>>();
    k_mark2<<<128, 256>>>();
    k_compact2<<<(BB*S2 + 255)/256, 256>>>();
    k_conv2a<<<1024, 256>>>(cb2);
    k_reduce_c2<<<128, 256>>>();
    k_u2<<<8, 256>>>(cb2);
    k_bn3fin<<<1, 256>>>(cg2, cbe2);
    k_xa<<<512, 256>>>(p_ya2, CO2, 3, 1);

    // conv3 dense (small) -> d_out
    k_t3c<<<216, 256>>>();
    k_conv3<<<BB*S3, 256>>>(cb3, out);
    k_reduce_out<<<256, 256>>>(out);
    k_bnparam<<<1, 256>>>(1152, 256, 1.f/(float)(BB*S3), cg3, cbe3, 4);
    k_bnrelu<<<(BB*CO3*S3 + 255)/256, 256>>>(out, BB*CO3*S3, 256, S3, 4);
}

// round 5
// speedup vs baseline: 1.9394x; 1.4990x over previous
#include <cuda_runtime.h>

// ---------------- problem dimensions (fixed by the dataset) ----------------
#define BB   2
#define NV   12000
#define NP   32
#define CINF 5
#define C1   64
#define C2   128
#define D0 20
#define H0 128
#define W0 128
#define S0 (D0*H0*W0)
#define D1 10
#define H1 64
#define W1 64
#define S1 (D1*H1*W1)
#define D2 5
#define H2 32
#define W2 32
#define S2 (D2*H2*W2)
#define D3 3
#define H3 16
#define W3 16
#define S3 (D3*H3*W3)
#define CO1 128
#define CO2 256
#define CO3 256
#define T1 32
#define T2 16
#define T3 16

// ---------------- static scratch ----------------
__device__ float g_f1[BB*NV*C1];
__device__ float g_f2[BB*NV*C2];
__device__ float g_mx[BB*NV*C1];
__device__ float g_mn[BB*NV*C1];
__device__ int   g_win[BB*S0];
__device__ int   g_act1[BB*S1];
__device__ int   g_idx1[BB*S1];
__device__ int   g_act2[BB*S2];
__device__ int   g_idx2[BB*S2];
__device__ int   g_list1[BB*S1];
__device__ int   g_list2[BB*S2];
__device__ int   g_cnt[16];                 // [0]=cnt1 [1]=cnt2 [2..9]=cls counts
__device__ float g_ya1[BB*S1*CO1];
__device__ float g_ya2[BB*S2*CO2];
__device__ float g_wT1[27*C2*CO1];
__device__ float g_wT2[27*CO1*CO2];
__device__ float g_wT3[27*CO2*CO3];
__device__ float g_w2T[C1*C2];
__device__ float g_t2[27*CO2];
__device__ float g_x2bg[8*CO2];
__device__ float g_t3c[8*27*CO3];
__device__ float g_bg1[CO1];
__device__ float g_stats[2048];
__device__ float g_a[5*256];
__device__ float g_c[5*256];

// ---------------- init ----------------
__global__ void k_init() {
    int tid = blockIdx.x * blockDim.x + threadIdx.x;
    int stride = gridDim.x * blockDim.x;
    for (int j = tid; j < BB*S0; j += stride) g_win[j] = -1;
    for (int j = tid; j < BB*S1; j += stride) { g_act1[j] = 0; g_idx1[j] = -1; }
    for (int j = tid; j < BB*S2; j += stride) { g_act2[j] = 0; g_idx2[j] = -1; }
    if (tid < 2048) g_stats[tid] = 0.f;
    if (tid < 16) g_cnt[tid] = 0;
}

// fused: winner scatter (last-write-wins via max idx) + conv1-output marking
__global__ void k_scatter(const int* __restrict__ vc) {
    int i = blockIdx.x * blockDim.x + threadIdx.x;
    if (i >= BB*NV) return;
    int b = i / NV, v = i % NV;
    int c0 = vc[i*3], c1 = vc[i*3+1], c2 = vc[i*3+2];
    if (c0 < 0 || c0 >= D0 || c1 < 0 || c1 >= H0 || c2 < 0 || c2 >= W0) return;
    atomicMax(&g_win[b*S0 + (c0*H0 + c1)*W0 + c2], v);
    int dlo = c0 >> 1, dhi = min((c0+1) >> 1, D1-1);
    int hlo = c1 >> 1, hhi = min((c1+1) >> 1, H1-1);
    int wlo = c2 >> 1, whi = min((c2+1) >> 1, W1-1);
    for (int d = dlo; d <= dhi; d++)
        for (int h = hlo; h <= hhi; h++)
            for (int w = wlo; w <= whi; w++)
                g_act1[b*S1 + (d*H1 + h)*W1 + w] = 1;
}

// ---------------- VFE1: stats + per-voxel pre-BN min/max in ONE pass ----------------
__global__ void k_vfe1_stats(const float* __restrict__ x,
                             const float* __restrict__ w1,
                             const float* __restrict__ b1) {
    __shared__ float sx[512*CINF];
    int co = threadIdx.x;  // 64
    int p0 = blockIdx.x * 512;
    for (int i = co; i < 512*CINF; i += 64) sx[i] = x[p0*CINF + i];
    __syncthreads();
    float w0 = w1[co*5], wa = w1[co*5+1], wb = w1[co*5+2], wc = w1[co*5+3], wd = w1[co*5+4];
    float bbv = b1[co];
    float s = 0.f, q = 0.f;
    int v0 = blockIdx.x * 16;
    for (int v = 0; v < 16; v++) {
        float mx = -1e30f, mn = 1e30f;
        for (int p = v*32; p < v*32+32; p++) {
            const float* xp = &sx[p*5];
            float y = bbv;
            y = fmaf(w0, xp[0], y); y = fmaf(wa, xp[1], y); y = fmaf(wb, xp[2], y);
            y = fmaf(wc, xp[3], y); y = fmaf(wd, xp[4], y);
            s += y; q += y*y;
            mx = fmaxf(mx, y); mn = fminf(mn, y);
        }
        g_mx[(v0+v)*C1 + co] = mx;
        g_mn[(v0+v)*C1 + co] = mn;
    }
    atomicAdd(&g_stats[co], s);
    atomicAdd(&g_stats[64+co], q);
}

__global__ void k_bnparam(int off, int C, float invN,
                          const float* __restrict__ g,
                          const float* __restrict__ be, int stage) {
    int c = threadIdx.x;
    if (c >= C) return;
    float mu  = g_stats[off+c] * invN;
    float var = g_stats[off+C+c] * invN - mu*mu;
    float a   = g[c] * rsqrtf(var + 1e-5f);
    g_a[stage*256+c] = a;
    g_c[stage*256+c] = be[c] - mu*a;
}

// monotonicity: max_p relu(a*y+c) = relu(a*(a>=0?max:min)+c)
__global__ void k_vfe1_fwd() {
    int i = blockIdx.x * blockDim.x + threadIdx.x;
    if (i >= BB*NV*C1) return;
    int c = i & 63;
    float a = g_a[c], cc = g_c[c];
    float pre = (a >= 0.f) ? g_mx[i] : g_mn[i];
    g_f1[i] = fmaxf(fmaf(a, pre, cc), 0.f);
}

// ---------------- all weight transposes in one launch ----------------
#define N0 (27*C2*CO1)
#define N1 (27*CO1*CO2)
#define N2 (27*CO2*CO3)
#define N3 (C1*C2)
__global__ void k_trans(const float* __restrict__ cw1, const float* __restrict__ cw2,
                        const float* __restrict__ cw3, const float* __restrict__ w2) {
    int i = blockIdx.x * blockDim.x + threadIdx.x;
    if (i < N0) {
        int co = i % CO1, rem = i / CO1;
        int ci = rem % C2, t = rem / C2;
        g_wT1[i] = __ldg(&cw1[(co*C2 + ci)*27 + t]);
        return;
    }
    i -= N0;
    if (i < N1) {
        int co = i % CO2, rem = i / CO2;
        int ci = rem % CO1, t = rem / CO1;
        g_wT2[i] = __ldg(&cw2[(co*CO1 + ci)*27 + t]);
        return;
    }
    i -= N1;
    if (i < N2) {
        int co = i % CO3, rem = i / CO3;
        int ci = rem % CO2, t = rem / CO2;
        g_wT3[i] = __ldg(&cw3[(co*CO2 + ci)*27 + t]);
        return;
    }
    i -= N2;
    if (i < N3) {
        int k = i / C2, co = i % C2;
        g_w2T[i] = __ldg(&w2[co*C1 + k]);
    }
}

// ---------------- VFE2 ----------------
__global__ void k_vfe2_pre(const float* __restrict__ b2) {
    __shared__ float sf[C1];
    int co = threadIdx.x;  // 128
    float s = 0.f, q = 0.f;
    float bbv = b2[co];
    int r0 = blockIdx.x * 32;
    for (int r = 0; r < 32; r++) {
        int row = r0 + r;
        __syncthreads();
        if (co < C1) sf[co] = g_f1[row*C1 + co];
        __syncthreads();
        float y = bbv;
#pragma unroll 16
        for (int k = 0; k < C1; k++) y = fmaf(sf[k], __ldg(&g_w2T[k*C2 + co]), y);
        g_f2[row*C2 + co] = y;
        s += y; q += y*y;
    }
    atomicAdd(&g_stats[128+co], s);
    atomicAdd(&g_stats[128+C2+co], q);
}

// ---------------- compaction (zeroes compact output rows inline) ----------------
__global__ void k_compact1() {
    int j = blockIdx.x * blockDim.x + threadIdx.x;
    if (j >= BB*S1) return;
    if (g_act1[j]) {
        int p = atomicAdd(&g_cnt[0], 1);
        g_list1[p] = j;
        g_idx1[j] = p;
        float4 z = make_float4(0.f, 0.f, 0.f, 0.f);
        float4* yp = (float4*)&g_ya1[p*CO1];
#pragma unroll
        for (int k = 0; k < CO1/4; k++) yp[k] = z;
    }
}

__global__ void k_mark2() {
    int cnt = g_cnt[0];
    int stride = gridDim.x * blockDim.x;
    for (int it = blockIdx.x * blockDim.x + threadIdx.x; it < cnt; it += stride) {
        int j = g_list1[it];
        int b = j / S1, s = j % S1;
        int d = s / (H1*W1), h = (s / W1) % H1, w = s % W1;
        int dlo = d >> 1, dhi = min((d+1) >> 1, D2-1);
        int hlo = h >> 1, hhi = min((h+1) >> 1, H2-1);
        int wlo = w >> 1, whi = min((w+1) >> 1, W2-1);
        for (int dd = dlo; dd <= dhi; dd++)
            for (int hh = hlo; hh <= hhi; hh++)
                for (int ww = wlo; ww <= whi; ww++)
                    g_act2[b*S2 + (dd*H2 + hh)*W2 + ww] = 1;
    }
}

__global__ void k_compact2() {
    int j = blockIdx.x * blockDim.x + threadIdx.x;
    if (j >= BB*S2) return;
    if (g_act2[j]) {
        int p = atomicAdd(&g_cnt[1], 1);
        g_list2[p] = j;
        g_idx2[j] = p;
        int s = j % S2;
        int od = s / (H2*W2), oh = (s / W2) % H2, ow = s % W2;
        int cls = (od==0 ? 1 : 0) | (oh==0 ? 2 : 0) | (ow==0 ? 4 : 0);
        atomicAdd(&g_cnt[2+cls], 1);
        float4 z = make_float4(0.f, 0.f, 0.f, 0.f);
        float4* yp = (float4*)&g_ya2[p*CO2];
#pragma unroll
        for (int k = 0; k < CO2/4; k++) yp[k] = z;
    }
}

// ---------------- conv1: 32-cell batches, 3 taps per block, atomic partials ----------------
__global__ void k_conv1a(const float* __restrict__ cb1) {
    __shared__ float sf[T1*C2];       // 16 KB
    __shared__ int srow[T1*3];
    int tid = threadIdx.x;            // 256
    int co = tid & 127, half = tid >> 7;
    int cnt = g_cnt[0];
    int nchunk = (cnt + T1 - 1) / T1;
    float a1 = g_a[256+co], c1 = g_c[256+co];
    float bb = __ldg(&cb1[co]);
    for (int wk = blockIdx.x; wk < nchunk*9; wk += gridDim.x) {
        int chunk = wk / 9, grp = wk % 9;
        int base = chunk * T1;
        int nc = min(T1, cnt - base);
        __syncthreads();
        for (int e = tid; e < T1*3; e += 256) {
            int cell = e / 3, tt = e % 3, t = grp*3 + tt;
            int r = -1;
            if (cell < nc) {
                int j = g_list1[base+cell];
                int b = j / S1, s = j % S1;
                int od = s/(H1*W1), oh = (s/W1)%H1, ow = s%W1;
                int kd = t/9, kh = (t/3)%3, kw = t%3;
                int id = 2*od-1+kd, ih = 2*oh-1+kh, iw = 2*ow-1+kw;
                if (id>=0 && id<D0 && ih>=0 && ih<H0 && iw>=0 && iw<W0) {
                    int v = g_win[b*S0 + (id*H0+ih)*W0 + iw];
                    if (v >= 0) r = b*NV + v;
                }
            }
            srow[e] = r;
        }
        __syncthreads();
        float acc[16];
#pragma unroll
        for (int q = 0; q < 16; q++) acc[q] = 0.f;
        bool anyblk = false;
        for (int tt = 0; tt < 3; tt++) {
            bool any = false;
            for (int cell = 0; cell < T1; cell++) if (srow[cell*3+tt] >= 0) { any = true; break; }
            if (!any) continue;                // uniform across block
            anyblk = true;
            int t = grp*3 + tt;
            __syncthreads();
            for (int e = tid; e < T1*C2; e += 256) {
                int cell = e >> 7;             // i == co (stride preserves low 7 bits)
                int r = srow[cell*3+tt];
                sf[e] = (r >= 0) ? fmaxf(fmaf(g_f2[r*C2 + co], a1, c1), 0.f) : 0.f;
            }
            __syncthreads();
            const float* wp = &g_wT1[t*C2*CO1 + co];
            for (int ci = 0; ci < C2; ci++) {
                float w = __ldg(wp + ci*CO1);
#pragma unroll
                for (int q = 0; q < 16; q++)
                    acc[q] = fmaf(sf[(half*16+q)*C2 + ci], w, acc[q]);
            }
        }
        if (grp == 0 || anyblk) {
            for (int q = 0; q < 16; q++) {
                int cell = half*16 + q;
                if (cell < nc) {
                    float v = acc[q] + (grp == 0 ? bb : 0.f);
                    atomicAdd(&g_ya1[(base+cell)*CO1 + co], v);
                }
            }
        }
    }
}

// reduce compact ya1 (rows x 128)
__global__ void k_reduce_c1() {
    __shared__ float ss[256], sq[256];
    int tid = threadIdx.x;
    int c = tid & 127, half = tid >> 7;
    int cnt = g_cnt[0];
    float s = 0.f, q = 0.f;
    for (int r = blockIdx.x*2 + half; r < cnt; r += gridDim.x*2) {
        float v = g_ya1[r*CO1 + c];
        s += v; q += v*v;
    }
    ss[tid] = s; sq[tid] = q;
    __syncthreads();
    if (tid < 128) {
        atomicAdd(&g_stats[384 + tid], ss[tid] + ss[tid+128]);
        atomicAdd(&g_stats[384 + 128 + tid], sq[tid] + sq[tid+128]);
    }
}

__global__ void k_bn2fin(const float* __restrict__ cb1,
                         const float* __restrict__ cg1,
                         const float* __restrict__ cbe1) {
    int c = threadIdx.x;  // 128
    float nin = (float)(BB*S1 - g_cnt[0]);
    float bb = cb1[c];
    float sum = g_stats[384+c] + nin*bb;
    float sq  = g_stats[384+128+c] + nin*bb*bb;
    float invN = 1.f / (float)(BB*S1);
    float mu = sum*invN;
    float var = sq*invN - mu*mu;
    float a = cg1[c] * rsqrtf(var + 1e-5f);
    float cc = cbe1[c] - mu*a;
    g_a[2*256+c] = a; g_c[2*256+c] = cc;
    g_bg1[c] = fmaxf(fmaf(bb, a, cc), 0.f);
}

__global__ void k_tmat2() {
    int t = blockIdx.x, co = threadIdx.x;  // 27 x 256
    float s = 0.f;
    const float* wp = &g_wT2[t*CO1*CO2 + co];
    for (int ci = 0; ci < CO1; ci++) s = fmaf(__ldg(&g_bg1[ci]), __ldg(wp + ci*CO2), s);
    g_t2[t*CO2 + co] = s;
}

// ---------------- conv2: 16-cell batches, 3 taps per block ----------------
__global__ void k_conv2a(const float* __restrict__ cb2) {
    __shared__ float sdx[T2*CO1];     // 8 KB
    __shared__ int srow[T2*3];
    __shared__ int spos[T2];
    int tid = threadIdx.x;            // 256 = CO2
    int co = tid;
    int ii = tid & 127;               // input-channel lane for sdx fills
    int cnt = g_cnt[1];
    int nchunk = (cnt + T2 - 1) / T2;
    float a2 = g_a[2*256+ii], c2 = g_c[2*256+ii], bg = g_bg1[ii];
    for (int wk = blockIdx.x; wk < nchunk*9; wk += gridDim.x) {
        int chunk = wk / 9, grp = wk % 9;
        int base = chunk * T2;
        int nc = min(T2, cnt - base);
        __syncthreads();
        for (int cell = tid; cell < T2; cell += 256) {
            int pk = 0;
            if (cell < nc) {
                int j = g_list2[base+cell];
                int s = j % S2;
                pk = ((s/(H2*W2)) << 16) | (((s/W2)%H2) << 8) | (s%W2);
            }
            spos[cell] = pk;
        }
        for (int e = tid; e < T2*3; e += 256) {
            int cell = e / 3, tt = e % 3, t = grp*3 + tt;
            int r = -1;
            if (cell < nc) {
                int j = g_list2[base+cell];
                int b = j / S2, s = j % S2;
                int od = s/(H2*W2), oh = (s/W2)%H2, ow = s%W2;
                int kd = t/9, kh = (t/3)%3, kw = t%3;
                int id = 2*od-1+kd, ih = 2*oh-1+kh, iw = 2*ow-1+kw;
                if (id>=0 && id<D1 && ih>=0 && ih<H1 && iw>=0 && iw<W1)
                    r = g_idx1[b*S1 + (id*H1+ih)*W1 + iw];
            }
            srow[e] = r;
        }
        __syncthreads();
        float acc[T2];
#pragma unroll
        for (int q = 0; q < T2; q++) acc[q] = 0.f;
        if (grp == 0) {
            float tcv[27];
#pragma unroll
            for (int t = 0; t < 27; t++) tcv[t] = __ldg(&g_t2[t*CO2 + co]);
            float bb = __ldg(&cb2[co]);
            for (int cell = 0; cell < nc; cell++) {
                int pk = spos[cell];
                int od = pk >> 16, oh = (pk >> 8) & 255, ow = pk & 255;
                float u = bb;
#pragma unroll
                for (int t = 0; t < 27; t++) {
                    int kd = t/9, kh = (t/3)%3, kw = t%3;
                    bool valid = !(od==0 && kd==0) && !(oh==0 && kh==0) && !(ow==0 && kw==0);
                    if (valid) u += tcv[t];
                }
                acc[cell] = u;
            }
        }
        bool anyblk = false;
        for (int tt = 0; tt < 3; tt++) {
            bool any = false;
            for (int cell = 0; cell < T2; cell++) if (srow[cell*3+tt] >= 0) { any = true; break; }
            if (!any) continue;
            anyblk = true;
            int t = grp*3 + tt;
            __syncthreads();
            for (int e = tid; e < T2*CO1; e += 256) {
                int cell = e >> 7;
                int r = srow[cell*3+tt];
                sdx[e] = (r >= 0) ? fmaxf(fmaf(g_ya1[r*CO1 + ii], a2, c2), 0.f) - bg : 0.f;
            }
            __syncthreads();
            const float* wp = &g_wT2[t*CO1*CO2 + co];
            for (int ci = 0; ci < CO1; ci++) {
                float w = __ldg(wp + ci*CO2);
#pragma unroll
                for (int q = 0; q < T2; q++)
                    acc[q] = fmaf(sdx[q*CO1 + ci], w, acc[q]);
            }
        }
        if (grp == 0 || anyblk) {
            for (int q = 0; q < nc; q++)
                atomicAdd(&g_ya2[(base+q)*CO2 + co], acc[q]);
        }
    }
}

__global__ void k_reduce_c2() {
    int c = threadIdx.x;  // 256
    int cnt = g_cnt[1];
    float s = 0.f, q = 0.f;
    for (int r = blockIdx.x; r < cnt; r += gridDim.x) {
        float v = g_ya2[r*CO2 + c];
        s += v; q += v*v;
    }
    atomicAdd(&g_stats[640 + c], s);
    atomicAdd(&g_stats[640 + 256 + c], q);
}

// stage3 BN finalize: per-class inactive constants computed inline
__global__ void k_bn3fin(const float* __restrict__ cb2,
                         const float* __restrict__ cg2,
                         const float* __restrict__ cbe2) {
    int c = threadIdx.x;  // 256
    float sum = g_stats[640+c], sq = g_stats[640+256+c];
    float bb = cb2[c];
    float tcv[27];
#pragma unroll
    for (int t = 0; t < 27; t++) tcv[t] = g_t2[t*CO2 + c];
    float uv[8];
#pragma unroll
    for (int cls = 0; cls < 8; cls++) {
        float u = bb;
#pragma unroll
        for (int t = 0; t < 27; t++) {
            int kd = t/9, kh = (t/3)%3, kw = t%3;
            bool valid = !((cls & 1) && kd == 0) && !((cls & 2) && kh == 0) && !((cls & 4) && kw == 0);
            if (valid) u += tcv[t];
        }
        uv[cls] = u;
        float tot = (float)(BB * ((cls&1)?1:(D2-1)) * ((cls&2)?1:(H2-1)) * ((cls&4)?1:(W2-1)));
        float nin = tot - (float)g_cnt[2+cls];
        sum += nin*u; sq += nin*u*u;
    }
    float invN = 1.f / (float)(BB*S2);
    float mu = sum*invN;
    float var = sq*invN - mu*mu;
    float a = cg2[c] * rsqrtf(var + 1e-5f);
    float cc = cbe2[c] - mu*a;
    g_a[3*256+c] = a; g_c[3*256+c] = cc;
#pragma unroll
    for (int cls = 0; cls < 8; cls++)
        g_x2bg[cls*CO2 + c] = fmaxf(fmaf(uv[cls], a, cc), 0.f);
}

// per-class per-tap conv3 constants; also zero-fills d_out for atomic accumulation
__global__ void k_t3c(float* __restrict__ out) {
    int tid0 = blockIdx.x * 256 + threadIdx.x;       // 216*256 = 55296
    for (int j = tid0; j < BB*CO3*S3; j += 216*256) out[j] = 0.f;
    int cls = blockIdx.x / 27, t = blockIdx.x % 27;
    int co = threadIdx.x;
    float s = 0.f;
    const float* xb = &g_x2bg[cls*CO2];
    const float* wp = &g_wT3[t*CO2*CO3 + co];
    for (int ci = 0; ci < CO2; ci++) s = fmaf(__ldg(&xb[ci]), __ldg(wp + ci*CO3), s);
    g_t3c[(cls*27 + t)*CO3 + co] = s;
}

// ---------------- conv3: dense 16-cell batches, 3 taps per block ----------------
__global__ void k_conv3(const float* __restrict__ cb3, float* __restrict__ out) {
    __shared__ float sdx[T3*CO2];     // 16 KB
    __shared__ int srow[T3*3];
    __shared__ int scl[T3*3];
    int tid = threadIdx.x;            // 256 = CO3
    int co = tid;
    int wk = blockIdx.x;              // 96 chunks * 9 groups = 864
    int chunk = wk / 9, grp = wk % 9;
    int base = chunk * T3;
    int b = base / S3;
    int sbase = base % S3;
    float a3 = g_a[3*256+co], c3 = g_c[3*256+co];
    for (int e = tid; e < T3*3; e += 256) {
        int cell = e / 3, tt = e % 3, t = grp*3 + tt;
        int s = sbase + cell;
        int od = s/(H3*W3), oh = (s/W3)%H3, ow = s%W3;
        int kd = t/9, kh = (t/3)%3, kw = t%3;
        int id = 2*od-1+kd, ih = 2*oh-1+kh, iw = 2*ow-1+kw;
        int r = -1, cl = 0;
        if (id>=0 && id<D2 && ih>=0 && ih<H2 && iw>=0 && iw<W2) {
            r = g_idx2[b*S2 + (id*H2+ih)*W2 + iw];
            cl = (id==0 ? 1 : 0) | (ih==0 ? 2 : 0) | (iw==0 ? 4 : 0);
        }
        srow[e] = r; scl[e] = cl;
    }
    __syncthreads();
    float acc[T3];
#pragma unroll
    for (int q = 0; q < T3; q++) acc[q] = 0.f;
    if (grp == 0) {
        float bb = __ldg(&cb3[co]);
        for (int cell = 0; cell < T3; cell++) {
            int s = sbase + cell;
            int od = s/(H3*W3), oh = (s/W3)%H3, ow = s%W3;
            float u = bb;
            for (int t = 0; t < 27; t++) {
                int kd = t/9, kh = (t/3)%3, kw = t%3;
                int id = 2*od-1+kd, ih = 2*oh-1+kh, iw = 2*ow-1+kw;
                if (id>=0 && id<D2 && ih>=0 && ih<H2 && iw>=0 && iw<W2) {
                    int cl = (id==0 ? 1 : 0) | (ih==0 ? 2 : 0) | (iw==0 ? 4 : 0);
                    u += __ldg(&g_t3c[(cl*27 + t)*CO3 + co]);
                }
            }
            acc[cell] = u;
        }
    }
    bool anyblk = false;
    for (int tt = 0; tt < 3; tt++) {
        bool any = false;
        for (int cell = 0; cell < T3; cell++) if (srow[cell*3+tt] >= 0) { any = true; break; }
        if (!any) continue;
        anyblk = true;
        int t = grp*3 + tt;
        __syncthreads();
        for (int e = tid; e < T3*CO2; e += 256) {
            int cell = e >> 8;                // i == tid
            int r = srow[cell*3+tt];
            int cl = scl[cell*3+tt];
            sdx[e] = (r >= 0)
                ? fmaxf(fmaf(g_ya2[r*CO2 + co], a3, c3), 0.f) - g_x2bg[cl*CO2 + co]
                : 0.f;
        }
        __syncthreads();
        const float* wp = &g_wT3[t*CO2*CO3 + co];
        for (int ci = 0; ci < CO2; ci++) {
            float w = __ldg(wp + ci*CO3);
#pragma unroll
            for (int q = 0; q < T3; q++)
                acc[q] = fmaf(sdx[q*CO2 + ci], w, acc[q]);
        }
    }
    if (grp == 0 || anyblk) {
        for (int q = 0; q < T3; q++) {
            int s = sbase + q;
            atomicAdd(&out[(b*CO3 + co)*S3 + s], acc[q]);
        }
    }
}

__global__ void k_reduce_out(const float* __restrict__ y) {
    __shared__ float ss[256], sq[256];
    int c = blockIdx.x, tid = threadIdx.x;
    float s = 0.f, q = 0.f;
    for (int i = tid; i < BB*S3; i += 256) {
        int b = i / S3, sp = i % S3;
        float v = y[(b*CO3 + c)*S3 + sp];
        s += v; q += v*v;
    }
    ss[tid] = s; sq[tid] = q;
    __syncthreads();
    for (int o = 128; o > 0; o >>= 1) {
        if (tid < o) { ss[tid] += ss[tid+o]; sq[tid] += sq[tid+o]; }
        __syncthreads();
    }
    if (tid == 0) { g_stats[1152 + c] = ss[0]; g_stats[1152 + 256 + c] = sq[0]; }
}

__global__ void k_bnrelu(float* __restrict__ y, int n, int C, int inner, int stage) {
    int i = blockIdx.x * blockDim.x + threadIdx.x;
    if (i >= n) return;
    int c = (i / inner) % C;
    y[i] = fmaxf(fmaf(y[i], g_a[stage*256+c], g_c[stage*256+c]), 0.f);
}

// ---------------- launch ----------------
extern "C" void kernel_launch(void* const* d_in, const int* in_sizes, int n_in,
                              void* d_out, int out_size) {
    int base = (n_in >= 25) ? 5 : 2;
    const float* vf  = (const float*)d_in[0];
    const int*   vc  = (const int*)d_in[1];
    const float* w1  = (const float*)d_in[base+0];
    const float* b1  = (const float*)d_in[base+1];
    const float* g1  = (const float*)d_in[base+2];
    const float* be1 = (const float*)d_in[base+3];
    const float* w2  = (const float*)d_in[base+4];
    const float* b2  = (const float*)d_in[base+5];
    const float* g2  = (const float*)d_in[base+6];
    const float* be2 = (const float*)d_in[base+7];
    const float* cw1 = (const float*)d_in[base+8];
    const float* cb1 = (const float*)d_in[base+9];
    const float* cg1 = (const float*)d_in[base+10];
    const float* cbe1= (const float*)d_in[base+11];
    const float* cw2 = (const float*)d_in[base+12];
    const float* cb2 = (const float*)d_in[base+13];
    const float* cg2 = (const float*)d_in[base+14];
    const float* cbe2= (const float*)d_in[base+15];
    const float* cw3 = (const float*)d_in[base+16];
    const float* cb3 = (const float*)d_in[base+17];
    const float* cg3 = (const float*)d_in[base+18];
    const float* cbe3= (const float*)d_in[base+19];
    float* out = (float*)d_out;

    k_init<<<1024, 256>>>();
    k_scatter<<<(BB*NV + 255)/256, 256>>>(vc);

    k_vfe1_stats<<<1500, 64>>>(vf, w1, b1);
    k_bnparam<<<1, 64>>>(0, 64, 1.f/768000.f, g1, be1, 0);
    k_vfe1_fwd<<<(BB*NV*C1 + 255)/256, 256>>>();

    k_trans<<<(N0+N1+N2+N3 + 255)/256, 256>>>(cw1, cw2, cw3, w2);
    k_vfe2_pre<<<750, 128>>>(b2);
    k_bnparam<<<1, 128>>>(128, 128, 1.f/24000.f, g2, be2, 1);

    k_compact1<<<(BB*S1 + 255)/256, 256>>>();
    k_conv1a<<<1024, 256>>>(cb1);
    k_reduce_c1<<<240, 256>>>();
    k_bn2fin<<<1, 128>>>(cb1, cg1, cbe1);

    k_tmat2<<<27, 256>>>();
    k_mark2<<<128, 256>>>();
    k_compact2<<<(BB*S2 + 255)/256, 256>>>();
    k_conv2a<<<512, 256>>>(cb2);
    k_reduce_c2<<<128, 256>>>();
    k_bn3fin<<<1, 256>>>(cb2, cg2, cbe2);

    k_t3c<<<216, 256>>>(out);
    k_conv3<<<(BB*S3/T3)*9, 256>>>(cb3, out);
    k_reduce_out<<<256, 256>>>(out);
    k_bnparam<<<1, 256>>>(1152, 256, 1.f/(float)(BB*S3), cg3, cbe3, 4);
    k_bnrelu<<<(BB*CO3*S3 + 255)/256, 256>>>(out, BB*CO3*S3, 256, S3, 4);
}

// round 12
// speedup vs baseline: 2.5160x; 1.2973x over previous
#include <cuda_runtime.h>

// ---------------- problem dimensions ----------------
#define BB   2
#define NV   12000
#define NP   32
#define CINF 5
#define C1   64
#define C2   128
#define D0 20
#define H0 128
#define W0 128
#define S0 (D0*H0*W0)
#define D1 10
#define H1 64
#define W1 64
#define S1 (D1*H1*W1)
#define D2 5
#define H2 32
#define W2 32
#define S2 (D2*H2*W2)
#define D3 3
#define H3 16
#define W3 16
#define S3 (D3*H3*W3)
#define CO1 128
#define CO2 256
#define CO3 256
#define T1 32
#define T2 16
#define T3 16

// stats: vfe1@0(64) vfe2@128/256 conv1@384/512 conv2@640/896 conv3@1152/1408

__device__ float g_f1[BB*NV*C1];
__device__ float g_f2[BB*NV*C2];
__device__ float g_mx[BB*NV*C1];
__device__ float g_mn[BB*NV*C1];
__device__ int   g_win[BB*S0];
__device__ int   g_act1[BB*S1];
__device__ int   g_idx1[BB*S1];
__device__ int   g_act2[BB*S2];
__device__ int   g_idx2[BB*S2];
__device__ int   g_list1[BB*S1];
__device__ int   g_list2[BB*S2];
__device__ int   g_cnt[16];
__device__ __align__(16) float g_ya1[BB*S1*CO1];
__device__ __align__(16) float g_ya2[BB*S2*CO2];
__device__ float g_wT1[27*C2*CO1];
__device__ float g_wT2[27*CO1*CO2];
__device__ float g_wT3[27*CO2*CO3];
__device__ float g_w2T[C1*C2];
__device__ float g_t2[27*CO2];
__device__ float g_x2bg[8*CO2];
__device__ float g_t3c[8*27*CO3];
__device__ float g_a3[CO3];
__device__ float g_c3[CO3];
__device__ float g_stats[2048];

// ---------------- init ----------------
__global__ void k_init() {
    int tid = blockIdx.x * blockDim.x + threadIdx.x;
    int stride = gridDim.x * blockDim.x;
    for (int j = tid; j < BB*S0; j += stride) g_win[j] = -1;
    for (int j = tid; j < BB*S1; j += stride) { g_act1[j] = 0; g_idx1[j] = -1; }
    for (int j = tid; j < BB*S2; j += stride) { g_act2[j] = 0; g_idx2[j] = -1; }
    if (tid < 2048) g_stats[tid] = 0.f;
    if (tid < 16) g_cnt[tid] = 0;
}

// winner scatter + conv1-output marking
__global__ void k_scatter(const int* __restrict__ vc) {
    int i = blockIdx.x * blockDim.x + threadIdx.x;
    if (i >= BB*NV) return;
    int b = i / NV, v = i % NV;
    int c0 = vc[i*3], c1 = vc[i*3+1], c2 = vc[i*3+2];
    if (c0 < 0 || c0 >= D0 || c1 < 0 || c1 >= H0 || c2 < 0 || c2 >= W0) return;
    atomicMax(&g_win[b*S0 + (c0*H0 + c1)*W0 + c2], v);
    int dlo = c0 >> 1, dhi = min((c0+1) >> 1, D1-1);
    int hlo = c1 >> 1, hhi = min((c1+1) >> 1, H1-1);
    int wlo = c2 >> 1, whi = min((c2+1) >> 1, W1-1);
    for (int d = dlo; d <= dhi; d++)
        for (int h = hlo; h <= hhi; h++)
            for (int w = wlo; w <= whi; w++)
                g_act1[b*S1 + (d*H1 + h)*W1 + w] = 1;
}

// ---------------- VFE1 stats + per-voxel pre-BN min/max (one input pass) ----------------
__global__ void k_vfe1_stats(const float* __restrict__ x,
                             const float* __restrict__ w1,
                             const float* __restrict__ b1) {
    __shared__ float sx[256*CINF];
    int co = threadIdx.x;  // 64
    int p0 = blockIdx.x * 256;
    for (int i = co; i < 256*CINF; i += 64) sx[i] = x[p0*CINF + i];
    __syncthreads();
    float w0 = w1[co*5], wa = w1[co*5+1], wb = w1[co*5+2], wc = w1[co*5+3], wd = w1[co*5+4];
    float bbv = b1[co];
    float s = 0.f, q = 0.f;
    int v0 = blockIdx.x * 8;
    for (int v = 0; v < 8; v++) {
        float mx = -1e30f, mn = 1e30f;
        for (int p = v*32; p < v*32+32; p++) {
            const float* xp = &sx[p*5];
            float y = bbv;
            y = fmaf(w0, xp[0], y); y = fmaf(wa, xp[1], y); y = fmaf(wb, xp[2], y);
            y = fmaf(wc, xp[3], y); y = fmaf(wd, xp[4], y);
            s += y; q += y*y;
            mx = fmaxf(mx, y); mn = fminf(mn, y);
        }
        g_mx[(v0+v)*C1 + co] = mx;
        g_mn[(v0+v)*C1 + co] = mn;
    }
    atomicAdd(&g_stats[co], s);
    atomicAdd(&g_stats[64+co], q);
}

// ---------------- fused: vfe1_fwd(inline BN) + weight transposes + compact1 ----------------
#define N0 (27*C2*CO1)
#define N1 (27*CO1*CO2)
#define N2 (27*CO2*CO3)
#define N3 (C1*C2)
#define FW_B 6000
#define TR_B ((N0+N1+N2+N3)/256)
__global__ void k_fuse1(const float* __restrict__ cw1, const float* __restrict__ cw2,
                        const float* __restrict__ cw3, const float* __restrict__ w2,
                        const float* __restrict__ g1, const float* __restrict__ be1) {
    __shared__ int wsum[8];
    __shared__ int sbase;
    int bid = blockIdx.x;
    if (bid < FW_B) {
        int i = bid*256 + threadIdx.x;
        if (i < BB*NV*C1) {
            int c = i & 63;
            float mu = g_stats[c] * (1.f/768000.f);
            float var = g_stats[64+c] * (1.f/768000.f) - mu*mu;
            float a = __ldg(&g1[c]) * rsqrtf(var + 1e-5f);
            float cc = __ldg(&be1[c]) - mu*a;
            float pre = (a >= 0.f) ? g_mx[i] : g_mn[i];
            g_f1[i] = fmaxf(fmaf(a, pre, cc), 0.f);
        }
        return;
    }
    if (bid < FW_B + TR_B) {
        int i = (bid - FW_B)*256 + threadIdx.x;
        if (i < N0) {
            int co = i % CO1, rem = i / CO1;
            int ci = rem % C2, t = rem / C2;
            g_wT1[i] = __ldg(&cw1[(co*C2 + ci)*27 + t]);
            return;
        }
        i -= N0;
        if (i < N1) {
            int co = i % CO2, rem = i / CO2;
            int ci = rem % CO1, t = rem / CO1;
            g_wT2[i] = __ldg(&cw2[(co*CO1 + ci)*27 + t]);
            return;
        }
        i -= N1;
        if (i < N2) {
            int co = i % CO3, rem = i / CO3;
            int ci = rem % CO2, t = rem / CO2;
            g_wT3[i] = __ldg(&cw3[(co*CO2 + ci)*27 + t]);
            return;
        }
        i -= N2;
        if (i < N3) {
            int k = i / C2, co = i % C2;
            g_w2T[i] = __ldg(&w2[co*C1 + k]);
        }
        return;
    }
    // compact1: block-sorted compaction via ballot scan
    {
        int j = (bid - FW_B - TR_B)*256 + threadIdx.x;   // exactly covers BB*S1
        int f = g_act1[j];
        int lane = threadIdx.x & 31, w = threadIdx.x >> 5;
        unsigned m = __ballot_sync(0xffffffffu, f);
        if (lane == 0) wsum[w] = __popc(m);
        __syncthreads();
        if (threadIdx.x == 0) {
            int t = 0;
            for (int k = 0; k < 8; k++) { int c = wsum[k]; wsum[k] = t; t += c; }
            sbase = atomicAdd(&g_cnt[0], t);
        }
        __syncthreads();
        if (f) {
            int p = sbase + wsum[w] + __popc(m & ((1u << lane) - 1u));
            g_list1[p] = j;
            g_idx1[j] = p;
            float4 z = make_float4(0.f,0.f,0.f,0.f);
            float4* yp = (float4*)&g_ya1[p*CO1];
#pragma unroll
            for (int k = 0; k < CO1/4; k++) yp[k] = z;
        }
    }
}

// ---------------- VFE2 pre-BN + stats ----------------
__global__ void k_vfe2_pre(const float* __restrict__ b2) {
    __shared__ float sf[C1];
    int co = threadIdx.x;  // 128
    float s = 0.f, q = 0.f;
    float bbv = b2[co];
    int r0 = blockIdx.x * 32;
    for (int r = 0; r < 32; r++) {
        int row = r0 + r;
        __syncthreads();
        if (co < C1) sf[co] = g_f1[row*C1 + co];
        __syncthreads();
        float y = bbv;
#pragma unroll 16
        for (int k = 0; k < C1; k++) y = fmaf(sf[k], __ldg(&g_w2T[k*C2 + co]), y);
        g_f2[row*C2 + co] = y;
        s += y; q += y*y;
    }
    atomicAdd(&g_stats[128+co], s);
    atomicAdd(&g_stats[256+co], q);
}

// ---------------- conv1 (inline vfe2-BN on loads) + mark2 tail ----------------
__global__ void k_conv1a(const float* __restrict__ cb1,
                         const float* __restrict__ g2, const float* __restrict__ be2) {
    __shared__ float sf[T1*C2];
    __shared__ int srow[T1*3];
    int tid = threadIdx.x;            // 256
    int co = tid & 127, half = tid >> 7;
    int cnt = g_cnt[0];
    int nchunk = (cnt + T1 - 1) / T1;
    float mu1 = g_stats[128+co] * (1.f/24000.f);
    float var1 = g_stats[256+co] * (1.f/24000.f) - mu1*mu1;
    float a1 = __ldg(&g2[co]) * rsqrtf(var1 + 1e-5f);
    float c1 = __ldg(&be2[co]) - mu1*a1;
    float bb = __ldg(&cb1[co]);
    for (int wk = blockIdx.x; wk < nchunk*9; wk += gridDim.x) {
        int chunk = wk / 9, grp = wk % 9;
        int base = chunk * T1;
        int nc = min(T1, cnt - base);
        __syncthreads();
        for (int e = tid; e < T1*3; e += 256) {
            int cell = e / 3, tt = e % 3, t = grp*3 + tt;
            int r = -1;
            if (cell < nc) {
                int j = g_list1[base+cell];
                int b = j / S1, s = j % S1;
                int od = s/(H1*W1), oh = (s/W1)%H1, ow = s%W1;
                int kd = t/9, kh = (t/3)%3, kw = t%3;
                int id = 2*od-1+kd, ih = 2*oh-1+kh, iw = 2*ow-1+kw;
                if (id>=0 && id<D0 && ih>=0 && ih<H0 && iw>=0 && iw<W0) {
                    int v = g_win[b*S0 + (id*H0+ih)*W0 + iw];
                    if (v >= 0) r = b*NV + v;
                }
            }
            srow[e] = r;
        }
        __syncthreads();
        float acc[16];
#pragma unroll
        for (int q = 0; q < 16; q++) acc[q] = 0.f;
        bool anyblk = false;
        for (int tt = 0; tt < 3; tt++) {
            bool any = false;
            for (int cell = 0; cell < T1; cell++) if (srow[cell*3+tt] >= 0) { any = true; break; }
            if (!any) continue;
            anyblk = true;
            int t = grp*3 + tt;
            __syncthreads();
            for (int e = tid; e < T1*C2; e += 256) {
                int cell = e >> 7;
                int r = srow[cell*3+tt];
                sf[e] = (r >= 0) ? fmaxf(fmaf(g_f2[r*C2 + co], a1, c1), 0.f) : 0.f;
            }
            __syncthreads();
            const float* wp = &g_wT1[t*C2*CO1 + co];
            for (int ci4 = 0; ci4 < C2/4; ci4++) {
                float w0 = __ldg(wp + (4*ci4+0)*CO1);
                float w1v = __ldg(wp + (4*ci4+1)*CO1);
                float w2v = __ldg(wp + (4*ci4+2)*CO1);
                float w3v = __ldg(wp + (4*ci4+3)*CO1);
#pragma unroll
                for (int q = 0; q < 16; q++) {
                    float4 v = *reinterpret_cast<const float4*>(&sf[(half*16+q)*C2 + 4*ci4]);
                    acc[q] = fmaf(v.x, w0, acc[q]);
                    acc[q] = fmaf(v.y, w1v, acc[q]);
                    acc[q] = fmaf(v.z, w2v, acc[q]);
                    acc[q] = fmaf(v.w, w3v, acc[q]);
                }
            }
        }
        if (grp == 0 || anyblk) {
            for (int q = 0; q < 16; q++) {
                int cell = half*16 + q;
                if (cell < nc) {
                    float v = acc[q] + (grp == 0 ? bb : 0.f);
                    atomicAdd(&g_ya1[(base+cell)*CO1 + co], v);
                }
            }
        }
    }
    // mark2 tail
    int gtid = blockIdx.x*256 + tid;
    for (int it = gtid; it < cnt; it += gridDim.x*256) {
        int j = g_list1[it];
        int b = j / S1, s = j % S1;
        int d = s / (H1*W1), h = (s / W1) % H1, w = s % W1;
        int dlo = d >> 1, dhi = min((d+1) >> 1, D2-1);
        int hlo = h >> 1, hhi = min((h+1) >> 1, H2-1);
        int wlo = w >> 1, whi = min((w+1) >> 1, W2-1);
        for (int dd = dlo; dd <= dhi; dd++)
            for (int hh = hlo; hh <= hhi; hh++)
                for (int ww = wlo; ww <= whi; ww++)
                    g_act2[b*S2 + (dd*H2 + hh)*W2 + ww] = 1;
    }
}

// ---------------- fused: reduce_c1 + compact2 ----------------
__global__ void k_fuse2() {
    __shared__ int wsum[8];
    __shared__ int sbase;
    if (blockIdx.x < 240) {
        __shared__ float ss[256], sq[256];
        int tid = threadIdx.x;
        int c = tid & 127, half = tid >> 7;
        int cnt = g_cnt[0];
        float s = 0.f, q = 0.f;
        for (int r = blockIdx.x*2 + half; r < cnt; r += 480) {
            float v = g_ya1[r*CO1 + c];
            s += v; q += v*v;
        }
        ss[tid] = s; sq[tid] = q;
        __syncthreads();
        if (tid < 128) {
            atomicAdd(&g_stats[384 + tid], ss[tid] + ss[tid+128]);
            atomicAdd(&g_stats[512 + tid], sq[tid] + sq[tid+128]);
        }
        return;
    }
    // compact2 (80 blocks cover BB*S2 = 20480)
    int j = (blockIdx.x - 240)*256 + threadIdx.x;
    int f = g_act2[j];
    int lane = threadIdx.x & 31, w = threadIdx.x >> 5;
    unsigned m = __ballot_sync(0xffffffffu, f);
    if (lane == 0) wsum[w] = __popc(m);
    __syncthreads();
    if (threadIdx.x == 0) {
        int t = 0;
        for (int k = 0; k < 8; k++) { int c = wsum[k]; wsum[k] = t; t += c; }
        sbase = atomicAdd(&g_cnt[1], t);
    }
    __syncthreads();
    if (f) {
        int p = sbase + wsum[w] + __popc(m & ((1u << lane) - 1u));
        g_list2[p] = j;
        g_idx2[j] = p;
        int s = j % S2;
        int od = s / (H2*W2), oh = (s / W2) % H2, ow = s % W2;
        int cls = (od==0 ? 1 : 0) | (oh==0 ? 2 : 0) | (ow==0 ? 4 : 0);
        atomicAdd(&g_cnt[2+cls], 1);
        float4 z = make_float4(0.f,0.f,0.f,0.f);
        float4* yp = (float4*)&g_ya2[p*CO2];
#pragma unroll
        for (int k = 0; k < CO2/4; k++) yp[k] = z;
    }
}

// stage-2 BN params (exact, analytic inactive term)
__device__ __forceinline__ void bn2_params(int c, const float* cb1, const float* cg1,
                                           const float* cbe1, float& a, float& cc, float& bg) {
    float nin = (float)(BB*S1 - g_cnt[0]);
    float bb = __ldg(&cb1[c]);
    float sum = g_stats[384+c] + nin*bb;
    float sq  = g_stats[512+c] + nin*bb*bb;
    float invN = 1.f / (float)(BB*S1);
    float mu = sum*invN;
    float var = sq*invN - mu*mu;
    a  = __ldg(&cg1[c]) * rsqrtf(var + 1e-5f);
    cc = __ldg(&cbe1[c]) - mu*a;
    bg = fmaxf(fmaf(bb, a, cc), 0.f);
}

__global__ void k_tmat2(const float* __restrict__ cb1, const float* __restrict__ cg1,
                        const float* __restrict__ cbe1) {
    __shared__ float sbg[CO1];
    int t = blockIdx.x, co = threadIdx.x;  // 27 x 256
    if (co < CO1) {
        float a, cc, bg;
        bn2_params(co, cb1, cg1, cbe1, a, cc, bg);
        sbg[co] = bg;
    }
    __syncthreads();
    float s = 0.f;
    const float* wp = &g_wT2[t*CO1*CO2 + co];
    for (int ci = 0; ci < CO1; ci++) s = fmaf(sbg[ci], __ldg(wp + ci*CO2), s);
    g_t2[t*CO2 + co] = s;
}

// ---------------- conv2 (inline stage-2 BN on loads) ----------------
__global__ void k_conv2a(const float* __restrict__ cb1, const float* __restrict__ cg1,
                         const float* __restrict__ cbe1, const float* __restrict__ cb2) {
    __shared__ float sdx[T2*CO1];
    __shared__ int srow[T2*3];
    __shared__ int spos[T2];
    int tid = threadIdx.x;            // 256
    int co = tid;
    int ii = tid & 127;
    int cnt = g_cnt[1];
    int nchunk = (cnt + T2 - 1) / T2;
    float a2, c2, bg;
    bn2_params(ii, cb1, cg1, cbe1, a2, c2, bg);
    for (int wk = blockIdx.x; wk < nchunk*9; wk += gridDim.x) {
        int chunk = wk / 9, grp = wk % 9;
        int base = chunk * T2;
        int nc = min(T2, cnt - base);
        __syncthreads();
        for (int cell = tid; cell < T2; cell += 256) {
            int pk = 0;
            if (cell < nc) {
                int j = g_list2[base+cell];
                int s = j % S2;
                pk = ((s/(H2*W2)) << 16) | (((s/W2)%H2) << 8) | (s%W2);
            }
            spos[cell] = pk;
        }
        for (int e = tid; e < T2*3; e += 256) {
            int cell = e / 3, tt = e % 3, t = grp*3 + tt;
            int r = -1;
            if (cell < nc) {
                int j = g_list2[base+cell];
                int b = j / S2, s = j % S2;
                int od = s/(H2*W2), oh = (s/W2)%H2, ow = s%W2;
                int kd = t/9, kh = (t/3)%3, kw = t%3;
                int id = 2*od-1+kd, ih = 2*oh-1+kh, iw = 2*ow-1+kw;
                if (id>=0 && id<D1 && ih>=0 && ih<H1 && iw>=0 && iw<W1)
                    r = g_idx1[b*S1 + (id*H1+ih)*W1 + iw];
            }
            srow[e] = r;
        }
        __syncthreads();
        float acc[T2];
#pragma unroll
        for (int q = 0; q < T2; q++) acc[q] = 0.f;
        if (grp == 0) {
            float tcv[27];
#pragma unroll
            for (int t = 0; t < 27; t++) tcv[t] = __ldg(&g_t2[t*CO2 + co]);
            float bb = __ldg(&cb2[co]);
            for (int cell = 0; cell < nc; cell++) {
                int pk = spos[cell];
                int od = pk >> 16, oh = (pk >> 8) & 255, ow = pk & 255;
                float u = bb;
#pragma unroll
                for (int t = 0; t < 27; t++) {
                    int kd = t/9, kh = (t/3)%3, kw = t%3;
                    bool valid = !(od==0 && kd==0) && !(oh==0 && kh==0) && !(ow==0 && kw==0);
                    if (valid) u += tcv[t];
                }
                acc[cell] = u;
            }
        }
        bool anyblk = false;
        for (int tt = 0; tt < 3; tt++) {
            bool any = false;
            for (int cell = 0; cell < T2; cell++) if (srow[cell*3+tt] >= 0) { any = true; break; }
            if (!any) continue;
            anyblk = true;
            int t = grp*3 + tt;
            __syncthreads();
            for (int e = tid; e < T2*CO1; e += 256) {
                int cell = e >> 7;
                int r = srow[cell*3+tt];
                sdx[e] = (r >= 0) ? fmaxf(fmaf(g_ya1[r*CO1 + ii], a2, c2), 0.f) - bg : 0.f;
            }
            __syncthreads();
            const float* wp = &g_wT2[t*CO1*CO2 + co];
            for (int ci4 = 0; ci4 < CO1/4; ci4++) {
                float w0 = __ldg(wp + (4*ci4+0)*CO2);
                float w1v = __ldg(wp + (4*ci4+1)*CO2);
                float w2v = __ldg(wp + (4*ci4+2)*CO2);
                float w3v = __ldg(wp + (4*ci4+3)*CO2);
#pragma unroll
                for (int q = 0; q < T2; q++) {
                    float4 v = *reinterpret_cast<const float4*>(&sdx[q*CO1 + 4*ci4]);
                    acc[q] = fmaf(v.x, w0, acc[q]);
                    acc[q] = fmaf(v.y, w1v, acc[q]);
                    acc[q] = fmaf(v.z, w2v, acc[q]);
                    acc[q] = fmaf(v.w, w3v, acc[q]);
                }
            }
        }
        if (grp == 0 || anyblk) {
            for (int q = 0; q < nc; q++)
                atomicAdd(&g_ya2[(base+q)*CO2 + co], acc[q]);
        }
    }
}

__global__ void k_reduce_c2() {
    int c = threadIdx.x;  // 256
    int cnt = g_cnt[1];
    float s = 0.f, q = 0.f;
    for (int r = blockIdx.x; r < cnt; r += gridDim.x) {
        float v = g_ya2[r*CO2 + c];
        s += v; q += v*v;
    }
    atomicAdd(&g_stats[640 + c], s);
    atomicAdd(&g_stats[896 + c], q);
}

// t3c + inline bn3fin + zero-fill of out
__global__ void k_t3c(const float* __restrict__ cb2, const float* __restrict__ cg2,
                      const float* __restrict__ cbe2, float* __restrict__ out) {
    __shared__ float sxb[CO2];
    int tid0 = blockIdx.x*256 + threadIdx.x;
    for (int j = tid0; j < BB*CO3*S3; j += 216*256) out[j] = 0.f;
    int cls = blockIdx.x / 27, t = blockIdx.x % 27;
    int c = threadIdx.x;
    float sum = g_stats[640+c], sq = g_stats[896+c];
    float bb = __ldg(&cb2[c]);
    float tcv[27];
#pragma unroll
    for (int k = 0; k < 27; k++) tcv[k] = g_t2[k*CO2 + c];
    float uown = 0.f;
#pragma unroll
    for (int cl = 0; cl < 8; cl++) {
        float u = bb;
#pragma unroll
        for (int k = 0; k < 27; k++) {
            int kd = k/9, kh = (k/3)%3, kw = k%3;
            bool valid = !((cl & 1) && kd == 0) && !((cl & 2) && kh == 0) && !((cl & 4) && kw == 0);
            if (valid) u += tcv[k];
        }
        if (cl == cls) uown = u;
        float tot = (float)(BB * ((cl&1)?1:(D2-1)) * ((cl&2)?1:(H2-1)) * ((cl&4)?1:(W2-1)));
        float nin = tot - (float)g_cnt[2+cl];
        sum += nin*u; sq += nin*u*u;
    }
    float invN = 1.f / (float)(BB*S2);
    float mu = sum*invN;
    float var = sq*invN - mu*mu;
    float a = __ldg(&cg2[c]) * rsqrtf(var + 1e-5f);
    float cc = __ldg(&cbe2[c]) - mu*a;
    float xb = fmaxf(fmaf(uown, a, cc), 0.f);
    sxb[c] = xb;
    if (t == 0) g_x2bg[cls*CO2 + c] = xb;
    if (blockIdx.x == 0) { g_a3[c] = a; g_c3[c] = cc; }
    __syncthreads();
    float s = 0.f;
    const float* wp = &g_wT3[t*CO2*CO3 + c];
    for (int ci = 0; ci < CO2; ci++) s = fmaf(sxb[ci], __ldg(wp + ci*CO3), s);
    g_t3c[(cls*27 + t)*CO3 + c] = s;
}

// ---------------- conv3: 4x4 spatial tiles, 3 taps/block ----------------
__global__ void k_conv3(const float* __restrict__ cb3, float* __restrict__ out) {
    __shared__ float sdx[T3*CO2];
    __shared__ int srow[T3*3];
    __shared__ int scl[T3*3];
    int tid = threadIdx.x;            // 256
    int co = tid;
    int wk = blockIdx.x;              // 96 chunks * 9 groups
    int chunk = wk / 9, grp = wk % 9;
    int b = chunk / 48;
    int rem = chunk % 48;
    int od = rem / 16, ohT = (rem / 4) % 4, owT = rem % 4;
    float a3 = g_a3[co], c3 = g_c3[co];
    for (int e = tid; e < T3*3; e += 256) {
        int cell = e / 3, tt = e % 3, t = grp*3 + tt;
        int oh = ohT*4 + (cell >> 2), ow = owT*4 + (cell & 3);
        int kd = t/9, kh = (t/3)%3, kw = t%3;
        int id = 2*od-1+kd, ih = 2*oh-1+kh, iw = 2*ow-1+kw;
        int r = -1, cl = 0;
        if (id>=0 && id<D2 && ih>=0 && ih<H2 && iw>=0 && iw<W2) {
            r = g_idx2[b*S2 + (id*H2+ih)*W2 + iw];
            cl = (id==0 ? 1 : 0) | (ih==0 ? 2 : 0) | (iw==0 ? 4 : 0);
        }
        srow[e] = r; scl[e] = cl;
    }
    __syncthreads();
    float acc[T3];
#pragma unroll
    for (int q = 0; q < T3; q++) acc[q] = 0.f;
    if (grp == 0) {
        float bb = __ldg(&cb3[co]);
        for (int cell = 0; cell < T3; cell++) {
            int oh = ohT*4 + (cell >> 2), ow = owT*4 + (cell & 3);
            float u = bb;
            for (int t = 0; t < 27; t++) {
                int kd = t/9, kh = (t/3)%3, kw = t%3;
                int id = 2*od-1+kd, ih = 2*oh-1+kh, iw = 2*ow-1+kw;
                if (id>=0 && id<D2 && ih>=0 && ih<H2 && iw>=0 && iw<W2) {
                    int cl = (id==0 ? 1 : 0) | (ih==0 ? 2 : 0) | (iw==0 ? 4 : 0);
                    u += __ldg(&g_t3c[(cl*27 + t)*CO3 + co]);
                }
            }
            acc[cell] = u;
        }
    }
    bool anyblk = false;
    for (int tt = 0; tt < 3; tt++) {
        bool any = false;
        for (int cell = 0; cell < T3; cell++) if (srow[cell*3+tt] >= 0) { any = true; break; }
        if (!any) continue;
        anyblk = true;
        int t = grp*3 + tt;
        __syncthreads();
        for (int e = tid; e < T3*CO2; e += 256) {
            int cell = e >> 8;
            int r = srow[cell*3+tt];
            int cl = scl[cell*3+tt];
            sdx[e] = (r >= 0)
                ? fmaxf(fmaf(g_ya2[r*CO2 + co], a3, c3), 0.f) - g_x2bg[cl*CO2 + co]
                : 0.f;
        }
        __syncthreads();
        const float* wp = &g_wT3[t*CO2*CO3 + co];
        for (int ci4 = 0; ci4 < CO2/4; ci4++) {
            float w0 = __ldg(wp + (4*ci4+0)*CO3);
            float w1v = __ldg(wp + (4*ci4+1)*CO3);
            float w2v = __ldg(wp + (4*ci4+2)*CO3);
            float w3v = __ldg(wp + (4*ci4+3)*CO3);
#pragma unroll
            for (int q = 0; q < T3; q++) {
                float4 v = *reinterpret_cast<const float4*>(&sdx[q*CO2 + 4*ci4]);
                acc[q] = fmaf(v.x, w0, acc[q]);
                acc[q] = fmaf(v.y, w1v, acc[q]);
                acc[q] = fmaf(v.z, w2v, acc[q]);
                acc[q] = fmaf(v.w, w3v, acc[q]);
            }
        }
    }
    if (grp == 0 || anyblk) {
        for (int q = 0; q < T3; q++) {
            int oh = ohT*4 + (q >> 2), ow = owT*4 + (q & 3);
            int s = od*H3*W3 + oh*W3 + ow;
            atomicAdd(&out[(b*CO3 + co)*S3 + s], acc[q]);
        }
    }
}

__global__ void k_reduce_out(const float* __restrict__ y) {
    __shared__ float ss[256], sq[256];
    int c = blockIdx.x, tid = threadIdx.x;
    float s = 0.f, q = 0.f;
    for (int i = tid; i < BB*S3; i += 256) {
        int b = i / S3, sp = i % S3;
        float v = y[(b*CO3 + c)*S3 + sp];
        s += v; q += v*v;
    }
    ss[tid] = s; sq[tid] = q;
    __syncthreads();
    for (int o = 128; o > 0; o >>= 1) {
        if (tid < o) { ss[tid] += ss[tid+o]; sq[tid] += sq[tid+o]; }
        __syncthreads();
    }
    if (tid == 0) { g_stats[1152 + c] = ss[0]; g_stats[1408 + c] = sq[0]; }
}

__global__ void k_out_bnrelu(float* __restrict__ y,
                             const float* __restrict__ cg3, const float* __restrict__ cbe3) {
    int i = blockIdx.x * blockDim.x + threadIdx.x;
    if (i >= BB*CO3*S3) return;
    int c = (i / S3) % CO3;
    float invN = 1.f / (float)(BB*S3);
    float mu = g_stats[1152+c] * invN;
    float var = g_stats[1408+c] * invN - mu*mu;
    float a = __ldg(&cg3[c]) * rsqrtf(var + 1e-5f);
    float cc = __ldg(&cbe3[c]) - mu*a;
    y[i] = fmaxf(fmaf(y[i], a, cc), 0.f);
}

// ---------------- launch ----------------
extern "C" void kernel_launch(void* const* d_in, const int* in_sizes, int n_in,
                              void* d_out, int out_size) {
    int base = (n_in >= 25) ? 5 : 2;
    const float* vf  = (const float*)d_in[0];
    const int*   vc  = (const int*)d_in[1];
    const float* w1  = (const float*)d_in[base+0];
    const float* b1  = (const float*)d_in[base+1];
    const float* g1  = (const float*)d_in[base+2];
    const float* be1 = (const float*)d_in[base+3];
    const float* w2  = (const float*)d_in[base+4];
    const float* b2  = (const float*)d_in[base+5];
    const float* g2  = (const float*)d_in[base+6];
    const float* be2 = (const float*)d_in[base+7];
    const float* cw1 = (const float*)d_in[base+8];
    const float* cb1 = (const float*)d_in[base+9];
    const float* cg1 = (const float*)d_in[base+10];
    const float* cbe1= (const float*)d_in[base+11];
    const float* cw2 = (const float*)d_in[base+12];
    const float* cb2 = (const float*)d_in[base+13];
    const float* cg2 = (const float*)d_in[base+14];
    const float* cbe2= (const float*)d_in[base+15];
    const float* cw3 = (const float*)d_in[base+16];
    const float* cb3 = (const float*)d_in[base+17];
    const float* cg3 = (const float*)d_in[base+18];
    const float* cbe3= (const float*)d_in[base+19];
    float* out = (float*)d_out;

    k_init<<<1024, 256>>>();
    k_scatter<<<(BB*NV + 255)/256, 256>>>(vc);
    k_vfe1_stats<<<3000, 64>>>(vf, w1, b1);
    k_fuse1<<<FW_B + TR_B + (BB*S1)/256, 256>>>(cw1, cw2, cw3, w2, g1, be1);
    k_vfe2_pre<<<750, 128>>>(b2);
    k_conv1a<<<1024, 256>>>(cb1, g2, be2);
    k_fuse2<<<240 + (BB*S2)/256, 256>>>();
    k_tmat2<<<27, 256>>>(cb1, cg1, cbe1);
    k_conv2a<<<512, 256>>>(cb1, cg1, cbe1, cb2);
    k_reduce_c2<<<128, 256>>>();
    k_t3c<<<216, 256>>>(cb2, cg2, cbe2, out);
    k_conv3<<<96*9, 256>>>(cb3, out);
    k_reduce_out<<<256, 256>>>(out);
    k_out_bnrelu<<<(BB*CO3*S3 + 255)/256, 256>>>(out, cg3, cbe3);
}